// round 7
// baseline (speedup 1.0000x reference)
#include <cuda_runtime.h>
#include <cuda_bf16.h>
#include <math.h>
#include <stdint.h>

#define B_ 32
#define T_ 2048
#define E_ 1024
#define A_ 1024
#define D_ 1024

typedef unsigned int u32;
typedef unsigned long long u64;

// ---------------- scratch (device globals; allocations forbidden) --------------
__device__ __align__(256) __nv_bfloat16 g_enc_hi[(size_t)B_ * T_ * E_];
__device__ __align__(256) __nv_bfloat16 g_enc_lo[(size_t)B_ * T_ * E_];
__device__ __align__(256) __nv_bfloat16 g_Wt_hi[A_ * E_];   // W^T [A,E], K-contiguous
__device__ __align__(256) __nv_bfloat16 g_Wt_lo[A_ * E_];
__device__ float g_dec_proj[B_ * A_];
__device__ float g_energy[B_ * T_];
__device__ float g_ctx_part[4 * B_ * E_];

// ---------------- PTX helpers (baseline ISA only: sm_80-class) ------------------
__device__ __forceinline__ u32 smem_u32(const void* p) {
    u32 a; asm("{ .reg .u64 t; cvta.to.shared.u64 t, %1; cvt.u32.u64 %0, t; }" : "=r"(a) : "l"(p));
    return a;
}
__device__ __forceinline__ void cpa16(u32 dst, const void* src) {
    asm volatile("cp.async.cg.shared.global [%0], [%1], 16;" :: "r"(dst), "l"(src));
}
#define CPA_COMMIT()  asm volatile("cp.async.commit_group;" ::: "memory")
#define CPA_WAIT(n)   asm volatile("cp.async.wait_group %0;" :: "n"(n) : "memory")

__device__ __forceinline__ void ldsm4(u32* r, u32 addr) {
    asm volatile("ldmatrix.sync.aligned.m8n8.x4.shared.b16 {%0,%1,%2,%3}, [%4];"
        : "=r"(r[0]), "=r"(r[1]), "=r"(r[2]), "=r"(r[3]) : "r"(addr));
}
__device__ __forceinline__ void mma_bf16(float* c, const u32* a, const u32* b) {
    asm volatile("mma.sync.aligned.m16n8k16.row.col.f32.bf16.bf16.f32 "
        "{%0,%1,%2,%3}, {%4,%5,%6,%7}, {%8,%9}, {%0,%1,%2,%3};"
        : "+f"(c[0]), "+f"(c[1]), "+f"(c[2]), "+f"(c[3])
        : "r"(a[0]), "r"(a[1]), "r"(a[2]), "r"(a[3]), "r"(b[0]), "r"(b[1]));
}

// tanh via 2 MUFU: tanh(x) = (e - 1)/(e + 1), e = 2^(2x*log2e)
__device__ __forceinline__ float fast_tanh(float x) {
    float xa = fminf(fmaxf(x, -12.0f), 12.0f);
    float e;
    asm("ex2.approx.f32 %0, %1;" : "=f"(e) : "f"(xa * 2.8853900817779268f));
    float r;
    asm("rcp.approx.f32 %0, %1;" : "=f"(r) : "f"(e + 1.0f));
    return (e - 1.0f) * r;
}

// ---------------- pass 0a: enc fp32 -> bf16 hi/lo ------------------------------
__global__ __launch_bounds__(256) void convert_enc_kernel(const float* __restrict__ enc) {
    size_t i = ((size_t)blockIdx.x * 256 + threadIdx.x) * 4;
    float4 x = *(const float4*)(enc + i);
    __nv_bfloat16 h0 = __float2bfloat16(x.x), h1 = __float2bfloat16(x.y);
    __nv_bfloat16 h2 = __float2bfloat16(x.z), h3 = __float2bfloat16(x.w);
    __nv_bfloat16 l0 = __float2bfloat16(x.x - __bfloat162float(h0));
    __nv_bfloat16 l1 = __float2bfloat16(x.y - __bfloat162float(h1));
    __nv_bfloat16 l2 = __float2bfloat16(x.z - __bfloat162float(h2));
    __nv_bfloat16 l3 = __float2bfloat16(x.w - __bfloat162float(h3));
    *(__nv_bfloat162*)(g_enc_hi + i)     = __nv_bfloat162(h0, h1);
    *(__nv_bfloat162*)(g_enc_hi + i + 2) = __nv_bfloat162(h2, h3);
    *(__nv_bfloat162*)(g_enc_lo + i)     = __nv_bfloat162(l0, l1);
    *(__nv_bfloat162*)(g_enc_lo + i + 2) = __nv_bfloat162(l2, l3);
}

// ---------------- pass 0b: W_enc [E,A] -> W^T [A,E] bf16 hi/lo ------------------
__global__ __launch_bounds__(256) void convert_wt_kernel(const float* __restrict__ W) {
    int idx = blockIdx.x * 256 + threadIdx.x;      // output-linear over [A,E]
    int a = idx >> 10, e = idx & 1023;
    float x = W[(size_t)e * A_ + a];
    __nv_bfloat16 h = __float2bfloat16(x);
    g_Wt_hi[idx] = h;
    g_Wt_lo[idx] = __float2bfloat16(x - __bfloat162float(h));
}

// ---------------- pass 1: dec_proj[b,a] = dec[b,:] . W_dec[:,a] + b_enc[a] ------
__global__ __launch_bounds__(256) void dec_proj_kernel(
    const float* __restrict__ dec_out, const float* __restrict__ W_dec,
    const float* __restrict__ b_enc)
{
    int b = blockIdx.y;
    int a = blockIdx.x * 256 + threadIdx.x;
    __shared__ float ds[D_];
    for (int i = threadIdx.x; i < D_; i += 256) ds[i] = dec_out[b * D_ + i];
    __syncthreads();
    float s = b_enc[a];
    #pragma unroll 8
    for (int d = 0; d < D_; ++d) s += ds[d] * W_dec[(size_t)d * A_ + a];
    g_dec_proj[b * A_ + a] = s;
}

// ---------------- pass 2: mma.sync split-bf16 GEMM + tanh + v-reduce ------------
// 256 thr = 8 warps (4M x 2N), 2 CTAs/SM. CTA tile M=128 x N=128/chunk, 8 chunks.
// K in KC=16 stages, 4-deep cp.async pipeline (wait_group(2), DMA issued 3 stages
// ahead => covers L2 latency), ONE __syncthreads per stage, flat prefetch across
// chunks. Rows 32B data + 16B pad => conflict-free ldmatrix.
// 3 MMA splits: hi*hi + hi*lo + lo*hi.
#define KC 16
#define NSTAGE (E_/KC)               // 64 per chunk
#define TOTSTG (8 * NSTAGE)          // 512 flat
#define NPIPE 4
#define ROWB 48                      // 32B data + 16B pad
#define SPLIT_SZ (128 * ROWB)        // 6144
#define STG_SZ (4 * SPLIT_SZ)        // 24576: Ahi, Alo, Bhi, Blo
#define ST_AH 0
#define ST_AL SPLIT_SZ
#define ST_BH (2 * SPLIT_SZ)
#define ST_BL (3 * SPLIT_SZ)
#define OF_DP (NPIPE * STG_SZ)       // 98304
#define OF_V  (OF_DP + 4096)
#define OF_RED (OF_V + 4096)
#define SMEM_TOTAL (OF_RED + 1024)   // 107520 -> 2 CTAs/SM

__device__ __forceinline__ void stage_in(u32 sb, int s,
                                         const char* encH, const char* encL, int tid)
{
    const u32 base = sb + (u32)(s & (NPIPE - 1)) * STG_SZ;
    const int kbyte = (s & (NSTAGE - 1)) * 32;   // 16 bf16 = 32B along k
    const int a0 = (s >> 6) * 128;               // N-chunk base
    const int row = tid >> 1, col = (tid & 1) * 16;
    const u32 so = (u32)(row * ROWB + col);
    size_t ga = (size_t)row * 2048 + kbyte + col;
    cpa16(base + ST_AH + so, encH + ga);
    cpa16(base + ST_AL + so, encL + ga);
    size_t gb = (size_t)(a0 + row) * 2048 + kbyte + col;
    cpa16(base + ST_BH + so, (const char*)g_Wt_hi + gb);
    cpa16(base + ST_BL + so, (const char*)g_Wt_lo + gb);
}

__global__ __launch_bounds__(256, 2) void energy_kernel(const float* __restrict__ v) {
    extern __shared__ char smem[];
    u32 sb = smem_u32(smem);
    const int tid  = threadIdx.x;
    const int lane = tid & 31, wid = tid >> 5;
    const int wm = wid >> 1, wn = wid & 1;
    const int m0 = blockIdx.x * 128;           // flattened (b*T + t) row base
    const int b  = m0 >> 11;

    float* dp_s = (float*)(smem + OF_DP);
    float* v_s  = (float*)(smem + OF_V);
    float* red  = (float*)(smem + OF_RED);
    for (int i = tid; i < A_; i += 256) {
        dp_s[i] = g_dec_proj[b * A_ + i];
        v_s[i]  = v[i];
    }

    const char* encH = (const char*)g_enc_hi + (size_t)m0 * 2048;
    const char* encL = (const char*)g_enc_lo + (size_t)m0 * 2048;

    // ldmatrix lane addressing (constant per thread), K=16 per stage
    const u32 a_off = (u32)((wm * 32 + (lane & 15)) * ROWB + ((lane >> 4) & 1) * 16);
    const u32 b_off = (u32)((wn * 64 + (lane & 7) + ((lane >> 4) & 1) * 8) * ROWB
                            + ((lane >> 3) & 1) * 16);

    float rowsum[4] = {0.f, 0.f, 0.f, 0.f};

    // prologue: issue pipeline depth-1 stages
    #pragma unroll
    for (int p = 0; p < NPIPE - 1; ++p) {
        stage_in(sb, p, encH, encL, tid);
        CPA_COMMIT();
    }

    for (int ch = 0; ch < 8; ++ch) {
        const int a0 = ch * 128;
        float c[2][8][4];
        #pragma unroll
        for (int tm = 0; tm < 2; ++tm)
            #pragma unroll
            for (int tn = 0; tn < 8; ++tn)
                #pragma unroll
                for (int q = 0; q < 4; ++q) c[tm][tn][q] = 0.f;

        for (int kc = 0; kc < NSTAGE; ++kc) {
            const int s = ch * NSTAGE + kc;
            CPA_WAIT(NPIPE - 2);        // stage s data landed
            __syncthreads();            // visible to all warps; frees buf (s-1)%4

            // prefetch 3 stages ahead (into the buffer freed by this barrier)
            if (s + NPIPE - 1 < TOTSTG) {
                stage_in(sb, s + NPIPE - 1, encH, encL, tid);
                CPA_COMMIT();
            }

            const u32 base = sb + (u32)(s & (NPIPE - 1)) * STG_SZ;
            u32 ah[2][4], al[2][4];
            #pragma unroll
            for (int tm = 0; tm < 2; ++tm) {
                u32 off = a_off + (u32)(tm * 16 * ROWB);
                ldsm4(ah[tm], base + ST_AH + off);
                ldsm4(al[tm], base + ST_AL + off);
            }
            #pragma unroll
            for (int p = 0; p < 4; ++p) {
                u32 off = b_off + (u32)(p * 16 * ROWB);
                u32 th[4], tl[4];
                ldsm4(th, base + ST_BH + off);
                ldsm4(tl, base + ST_BL + off);
                #pragma unroll
                for (int tm = 0; tm < 2; ++tm) {
                    mma_bf16(c[tm][2*p],   ah[tm], th);
                    mma_bf16(c[tm][2*p],   ah[tm], tl);
                    mma_bf16(c[tm][2*p],   al[tm], th);
                    mma_bf16(c[tm][2*p+1], ah[tm], th + 2);
                    mma_bf16(c[tm][2*p+1], ah[tm], tl + 2);
                    mma_bf16(c[tm][2*p+1], al[tm], th + 2);
                }
            }
        }

        // epilogue (register-only): tanh(c + dec_proj) . v into per-row partials
        #pragma unroll
        for (int tm = 0; tm < 2; ++tm)
            #pragma unroll
            for (int tn = 0; tn < 8; ++tn) {
                int n = a0 + wn * 64 + tn * 8 + 2 * (lane & 3);
                float d0 = dp_s[n], d1 = dp_s[n + 1];
                float v0 = v_s[n],  v1 = v_s[n + 1];
                rowsum[tm*2+0] += fast_tanh(c[tm][tn][0] + d0) * v0
                                + fast_tanh(c[tm][tn][1] + d1) * v1;
                rowsum[tm*2+1] += fast_tanh(c[tm][tn][2] + d0) * v0
                                + fast_tanh(c[tm][tn][3] + d1) * v1;
            }
    }

    // reduce across the 4 lanes of each quad (disjoint n-columns)
    #pragma unroll
    for (int i = 0; i < 4; ++i) {
        float s = rowsum[i];
        s += __shfl_xor_sync(0xffffffffu, s, 1);
        s += __shfl_xor_sync(0xffffffffu, s, 2);
        rowsum[i] = s;
    }
    if ((lane & 3) == 0) {
        int r0 = lane >> 2;
        int rb = wn * 128 + wm * 32;
        red[rb + r0]          = rowsum[0];
        red[rb + r0 + 8]      = rowsum[1];
        red[rb + 16 + r0]     = rowsum[2];
        red[rb + 16 + r0 + 8] = rowsum[3];
    }
    __syncthreads();
    if (tid < 128) g_energy[m0 + tid] = red[tid] + red[128 + tid];
}

// ---------------- pass 3: masked (0/1) softmax over T ---------------------------
__global__ __launch_bounds__(256) void softmax_kernel(
    const int* __restrict__ x_lens, float* __restrict__ att)
{
    int b = blockIdx.x, tid = threadIdx.x;
    __shared__ float sm[T_];
    __shared__ float red[256];
    int len = x_lens[b];

    float mx = -3.4e38f;
    for (int t = tid; t < T_; t += 256) {
        float e = g_energy[b * T_ + t];
        e = (t < len) ? e : 0.0f;      // reference multiplies by 0/1 mask
        sm[t] = e;
        mx = fmaxf(mx, e);
    }
    red[tid] = mx; __syncthreads();
    for (int s = 128; s > 0; s >>= 1) {
        if (tid < s) red[tid] = fmaxf(red[tid], red[tid + s]);
        __syncthreads();
    }
    mx = red[0];
    __syncthreads();

    float lsum = 0.f;
    for (int t = tid; t < T_; t += 256) {
        float e = expf(sm[t] - mx);
        sm[t] = e;
        lsum += e;
    }
    red[tid] = lsum; __syncthreads();
    for (int s = 128; s > 0; s >>= 1) {
        if (tid < s) red[tid] += red[tid + s];
        __syncthreads();
    }
    float inv = 1.0f / red[0];
    for (int t = tid; t < T_; t += 256) att[b * T_ + t] = sm[t] * inv;
}

// ---------------- pass 4: context partials over T segments ----------------------
__global__ __launch_bounds__(128) void context_part_kernel(
    const float* __restrict__ enc, const float* __restrict__ att)
{
    int b = blockIdx.y, seg = blockIdx.z;
    int e = blockIdx.x * 128 + threadIdx.x;
    __shared__ float as_[T_ / 4];
    int t0 = seg * (T_ / 4);
    for (int t = threadIdx.x; t < T_ / 4; t += 128) as_[t] = att[b * T_ + t0 + t];
    __syncthreads();
    const float* ep = enc + ((size_t)b * T_ + t0) * E_ + e;
    float s = 0.f;
    #pragma unroll 8
    for (int t = 0; t < T_ / 4; ++t) s += ep[(size_t)t * E_] * as_[t];
    g_ctx_part[((size_t)seg * B_ + b) * E_ + e] = s;
}

__global__ __launch_bounds__(256) void context_reduce_kernel(float* __restrict__ ctx) {
    int i = blockIdx.x * 256 + threadIdx.x;      // over B_*E_
    ctx[i] = g_ctx_part[i] + g_ctx_part[B_ * E_ + i]
           + g_ctx_part[2 * B_ * E_ + i] + g_ctx_part[3 * B_ * E_ + i];
}

// ---------------- launch -------------------------------------------------------
extern "C" void kernel_launch(void* const* d_in, const int* in_sizes, int n_in,
                              void* d_out, int out_size)
{
    const float* enc     = (const float*)d_in[0];  // [B,T,E]
    const int*   x_lens  = (const int*)  d_in[1];  // [B]
    const float* dec_out = (const float*)d_in[2];  // [B,1,D]
    // d_in[3] att_weights_step: unused by reference
    const float* W_enc   = (const float*)d_in[4];  // [E,A]
    const float* b_enc   = (const float*)d_in[5];  // [A]
    const float* W_dec   = (const float*)d_in[6];  // [D,A]
    const float* v       = (const float*)d_in[7];  // [A]

    float* ctx = (float*)d_out;            // [B,1,E]
    float* att = (float*)d_out + B_ * E_;  // [B,T]

    cudaFuncSetAttribute(energy_kernel,
                         cudaFuncAttributeMaxDynamicSharedMemorySize, SMEM_TOTAL);

    convert_enc_kernel<<<(B_ * T_ * E_) / (256 * 4), 256>>>(enc);
    convert_wt_kernel <<<(A_ * E_) / 256, 256>>>(W_enc);
    dec_proj_kernel   <<<dim3(A_ / 256, B_), 256>>>(dec_out, W_dec, b_enc);
    energy_kernel     <<<(B_ * T_) / 128, 256, SMEM_TOTAL>>>(v);
    softmax_kernel    <<<B_, 256>>>(x_lens, att);
    context_part_kernel<<<dim3(E_ / 128, B_, 4), 128>>>(enc, att);
    context_reduce_kernel<<<(B_ * E_) / 256, 256>>>(ctx);
}

// round 8
// speedup vs baseline: 1.0924x; 1.0924x over previous
#include <cuda_runtime.h>
#include <cuda_bf16.h>
#include <math.h>
#include <stdint.h>

#define B_ 32
#define T_ 2048
#define E_ 1024
#define A_ 1024
#define D_ 1024

typedef unsigned int u32;
typedef unsigned long long u64;

// ---------------- scratch (device globals; allocations forbidden) --------------
__device__ __align__(256) __nv_bfloat16 g_enc_hi[(size_t)B_ * T_ * E_];
__device__ __align__(256) __nv_bfloat16 g_enc_lo[(size_t)B_ * T_ * E_];
__device__ __align__(256) __nv_bfloat16 g_Wt_hi[A_ * E_];   // W^T [A,E], K-contiguous
__device__ __align__(256) __nv_bfloat16 g_Wt_lo[A_ * E_];
__device__ float g_dec_proj[B_ * A_];
__device__ float g_energy[B_ * T_];
__device__ float g_ctx_part[4 * B_ * E_];

// ---------------- PTX helpers (baseline ISA only: sm_80-class) ------------------
__device__ __forceinline__ u32 smem_u32(const void* p) {
    u32 a; asm("{ .reg .u64 t; cvta.to.shared.u64 t, %1; cvt.u32.u64 %0, t; }" : "=r"(a) : "l"(p));
    return a;
}
__device__ __forceinline__ void cpa16(u32 dst, const void* src) {
    asm volatile("cp.async.cg.shared.global [%0], [%1], 16;" :: "r"(dst), "l"(src));
}
#define CPA_COMMIT()  asm volatile("cp.async.commit_group;" ::: "memory")
#define CPA_WAIT(n)   asm volatile("cp.async.wait_group %0;" :: "n"(n) : "memory")

__device__ __forceinline__ void ldsm4(u32* r, u32 addr) {
    asm volatile("ldmatrix.sync.aligned.m8n8.x4.shared.b16 {%0,%1,%2,%3}, [%4];"
        : "=r"(r[0]), "=r"(r[1]), "=r"(r[2]), "=r"(r[3]) : "r"(addr));
}
__device__ __forceinline__ void mma_bf16(float* c, const u32* a, const u32* b) {
    asm volatile("mma.sync.aligned.m16n8k16.row.col.f32.bf16.bf16.f32 "
        "{%0,%1,%2,%3}, {%4,%5,%6,%7}, {%8,%9}, {%0,%1,%2,%3};"
        : "+f"(c[0]), "+f"(c[1]), "+f"(c[2]), "+f"(c[3])
        : "r"(a[0]), "r"(a[1]), "r"(a[2]), "r"(a[3]), "r"(b[0]), "r"(b[1]));
}

// tanh via 2 MUFU: tanh(x) = (e - 1)/(e + 1), e = 2^(2x*log2e)
__device__ __forceinline__ float fast_tanh(float x) {
    float xa = fminf(fmaxf(x, -12.0f), 12.0f);
    float e;
    asm("ex2.approx.f32 %0, %1;" : "=f"(e) : "f"(xa * 2.8853900817779268f));
    float r;
    asm("rcp.approx.f32 %0, %1;" : "=f"(r) : "f"(e + 1.0f));
    return (e - 1.0f) * r;
}

// ---------------- pass 0a: enc fp32 -> bf16 hi/lo ------------------------------
__global__ __launch_bounds__(256) void convert_enc_kernel(const float* __restrict__ enc) {
    size_t i = ((size_t)blockIdx.x * 256 + threadIdx.x) * 4;
    float4 x = *(const float4*)(enc + i);
    __nv_bfloat16 h0 = __float2bfloat16(x.x), h1 = __float2bfloat16(x.y);
    __nv_bfloat16 h2 = __float2bfloat16(x.z), h3 = __float2bfloat16(x.w);
    __nv_bfloat16 l0 = __float2bfloat16(x.x - __bfloat162float(h0));
    __nv_bfloat16 l1 = __float2bfloat16(x.y - __bfloat162float(h1));
    __nv_bfloat16 l2 = __float2bfloat16(x.z - __bfloat162float(h2));
    __nv_bfloat16 l3 = __float2bfloat16(x.w - __bfloat162float(h3));
    *(__nv_bfloat162*)(g_enc_hi + i)     = __nv_bfloat162(h0, h1);
    *(__nv_bfloat162*)(g_enc_hi + i + 2) = __nv_bfloat162(h2, h3);
    *(__nv_bfloat162*)(g_enc_lo + i)     = __nv_bfloat162(l0, l1);
    *(__nv_bfloat162*)(g_enc_lo + i + 2) = __nv_bfloat162(l2, l3);
}

// ---------------- pass 0b: W_enc [E,A] -> W^T [A,E] bf16 hi/lo ------------------
__global__ __launch_bounds__(256) void convert_wt_kernel(const float* __restrict__ W) {
    int idx = blockIdx.x * 256 + threadIdx.x;      // output-linear over [A,E]
    int a = idx >> 10, e = idx & 1023;
    float x = W[(size_t)e * A_ + a];
    __nv_bfloat16 h = __float2bfloat16(x);
    g_Wt_hi[idx] = h;
    g_Wt_lo[idx] = __float2bfloat16(x - __bfloat162float(h));
}

// ---------------- pass 1: dec_proj[b,a] = dec[b,:] . W_dec[:,a] + b_enc[a] ------
__global__ __launch_bounds__(256) void dec_proj_kernel(
    const float* __restrict__ dec_out, const float* __restrict__ W_dec,
    const float* __restrict__ b_enc)
{
    int b = blockIdx.y;
    int a = blockIdx.x * 256 + threadIdx.x;
    __shared__ float ds[D_];
    for (int i = threadIdx.x; i < D_; i += 256) ds[i] = dec_out[b * D_ + i];
    __syncthreads();
    float s = b_enc[a];
    #pragma unroll 8
    for (int d = 0; d < D_; ++d) s += ds[d] * W_dec[(size_t)d * A_ + a];
    g_dec_proj[b * A_ + a] = s;
}

// ---------------- pass 2: mma.sync split-bf16 GEMM + tanh + v-reduce ------------
// 256 thr = 8 warps (4M x 2N), 2 CTAs/SM. CTA tile M=128 x N=128/chunk, 8 chunks.
// KC=32 stages in a depth-3 cp.async ring => ONE __syncthreads per stage.
// Rows are 64B with granule-XOR swizzle off(row,g)=row*64+((g^(row>>1))&3)*16:
// conflict-free ldmatrix without padding (stage = 32KB, 3 stages fit 2 CTAs/SM).
// 3 MMA splits: hi*hi + hi*lo + lo*hi.
#define KC 32
#define NSTAGE (E_/KC)               // 32 per chunk
#define TOTSTG (8 * NSTAGE)          // 256 flat
#define NPIPE 3
#define ROWB 64
#define SPLIT_SZ (128 * ROWB)        // 8192
#define STG_SZ (4 * SPLIT_SZ)        // 32768: Ahi, Alo, Bhi, Blo
#define ST_AH 0
#define ST_AL SPLIT_SZ
#define ST_BH (2 * SPLIT_SZ)
#define ST_BL (3 * SPLIT_SZ)
#define OF_DP (NPIPE * STG_SZ)       // 98304
#define OF_V  (OF_DP + 4096)
#define OF_RED (OF_V + 4096)
#define SMEM_TOTAL (OF_RED + 1024)   // 107520 -> 2 CTAs/SM

// stage buffer index for flat stage s (mod 3 without div)
__device__ __forceinline__ u32 mod3(u32 s) { return s % 3u; }

__device__ __forceinline__ void stage_in(u32 sb, int s,
                                         const char* encH, const char* encL, int tid)
{
    const u32 base = sb + mod3((u32)s) * STG_SZ;
    const int kbyte = (s & (NSTAGE - 1)) * 64;   // 32 bf16 = 64B along k
    const int a0 = (s >> 5) * 128;               // N-chunk base
    const int row = tid >> 1;
    const int xr  = (row >> 1) & 3;
    #pragma unroll
    for (int q = 0; q < 2; ++q) {
        const int g  = (tid & 1) * 2 + q;        // granule 0..3 along k
        const u32 so = (u32)(row * ROWB + ((g ^ xr) & 3) * 16);
        const int gc = kbyte + g * 16;
        size_t ga = (size_t)row * 2048 + gc;
        cpa16(base + ST_AH + so, encH + ga);
        cpa16(base + ST_AL + so, encL + ga);
        size_t gb = (size_t)(a0 + row) * 2048 + gc;
        cpa16(base + ST_BH + so, (const char*)g_Wt_hi + gb);
        cpa16(base + ST_BL + so, (const char*)g_Wt_lo + gb);
    }
}

__global__ __launch_bounds__(256, 2) void energy_kernel(const float* __restrict__ v) {
    extern __shared__ char smem[];
    u32 sb = smem_u32(smem);
    const int tid  = threadIdx.x;
    const int lane = tid & 31, wid = tid >> 5;
    const int wm = wid >> 1, wn = wid & 1;
    const int m0 = blockIdx.x * 128;           // flattened (b*T + t) row base
    const int b  = m0 >> 11;

    float* dp_s = (float*)(smem + OF_DP);
    float* v_s  = (float*)(smem + OF_V);
    float* red  = (float*)(smem + OF_RED);
    for (int i = tid; i < A_; i += 256) {
        dp_s[i] = g_dec_proj[b * A_ + i];
        v_s[i]  = v[i];
    }

    const char* encH = (const char*)g_enc_hi + (size_t)m0 * 2048;
    const char* encL = (const char*)g_enc_lo + (size_t)m0 * 2048;

    // ldmatrix lane addressing with XOR swizzle. A: row = wm*32+(lane&15)+tm*16,
    // k-granule = ks*2 + ((lane>>4)&1). B: row = wn*64+(lane&7)+((lane>>4)&1)*8+p*16,
    // k-granule = ks*2 + ((lane>>3)&1).
    u32 a_base[2], a_xr[2];
    #pragma unroll
    for (int tm = 0; tm < 2; ++tm) {
        int r = wm * 32 + (lane & 15) + tm * 16;
        a_base[tm] = (u32)(r * ROWB);
        a_xr[tm]   = (u32)((r >> 1) & 3);
    }
    const u32 a_gbit = (u32)((lane >> 4) & 1);
    u32 b_base[4], b_xr[4];
    #pragma unroll
    for (int p = 0; p < 4; ++p) {
        int r = wn * 64 + (lane & 7) + ((lane >> 4) & 1) * 8 + p * 16;
        b_base[p] = (u32)(r * ROWB);
        b_xr[p]   = (u32)((r >> 1) & 3);
    }
    const u32 b_gbit = (u32)((lane >> 3) & 1);

    float rowsum[4] = {0.f, 0.f, 0.f, 0.f};

    // prologue: fill pipeline depth-1 stages
    #pragma unroll
    for (int p = 0; p < NPIPE - 1; ++p) {
        stage_in(sb, p, encH, encL, tid);
        CPA_COMMIT();
    }

    for (int ch = 0; ch < 8; ++ch) {
        const int a0 = ch * 128;
        float c[2][8][4];
        #pragma unroll
        for (int tm = 0; tm < 2; ++tm)
            #pragma unroll
            for (int tn = 0; tn < 8; ++tn)
                #pragma unroll
                for (int q = 0; q < 4; ++q) c[tm][tn][q] = 0.f;

        for (int kc = 0; kc < NSTAGE; ++kc) {
            const int s = ch * NSTAGE + kc;
            CPA_WAIT(NPIPE - 2);        // stage s landed
            __syncthreads();            // single barrier: also proves buf (s+2)%3 free

            if (s + NPIPE - 1 < TOTSTG) {
                stage_in(sb, s + NPIPE - 1, encH, encL, tid);
                CPA_COMMIT();
            }

            const u32 base = sb + mod3((u32)s) * STG_SZ;
            #pragma unroll
            for (int ks = 0; ks < 2; ++ks) {
                const u32 ga = (u32)(ks * 2) + a_gbit;
                const u32 gb = (u32)(ks * 2) + b_gbit;
                u32 ah[2][4], al[2][4];
                #pragma unroll
                for (int tm = 0; tm < 2; ++tm) {
                    u32 off = a_base[tm] + ((ga ^ a_xr[tm]) & 3) * 16;
                    ldsm4(ah[tm], base + ST_AH + off);
                    ldsm4(al[tm], base + ST_AL + off);
                }
                #pragma unroll
                for (int p = 0; p < 4; ++p) {
                    u32 off = b_base[p] + ((gb ^ b_xr[p]) & 3) * 16;
                    u32 th[4], tl[4];
                    ldsm4(th, base + ST_BH + off);
                    ldsm4(tl, base + ST_BL + off);
                    #pragma unroll
                    for (int tm = 0; tm < 2; ++tm) {
                        mma_bf16(c[tm][2*p],   ah[tm], th);
                        mma_bf16(c[tm][2*p],   ah[tm], tl);
                        mma_bf16(c[tm][2*p],   al[tm], th);
                        mma_bf16(c[tm][2*p+1], ah[tm], th + 2);
                        mma_bf16(c[tm][2*p+1], ah[tm], tl + 2);
                        mma_bf16(c[tm][2*p+1], al[tm], th + 2);
                    }
                }
            }
        }

        // epilogue (register-only): tanh(c + dec_proj) . v into per-row partials
        #pragma unroll
        for (int tm = 0; tm < 2; ++tm)
            #pragma unroll
            for (int tn = 0; tn < 8; ++tn) {
                int n = a0 + wn * 64 + tn * 8 + 2 * (lane & 3);
                float d0 = dp_s[n], d1 = dp_s[n + 1];
                float v0 = v_s[n],  v1 = v_s[n + 1];
                rowsum[tm*2+0] += fast_tanh(c[tm][tn][0] + d0) * v0
                                + fast_tanh(c[tm][tn][1] + d1) * v1;
                rowsum[tm*2+1] += fast_tanh(c[tm][tn][2] + d0) * v0
                                + fast_tanh(c[tm][tn][3] + d1) * v1;
            }
    }

    // reduce across the 4 lanes of each quad (disjoint n-columns)
    #pragma unroll
    for (int i = 0; i < 4; ++i) {
        float s = rowsum[i];
        s += __shfl_xor_sync(0xffffffffu, s, 1);
        s += __shfl_xor_sync(0xffffffffu, s, 2);
        rowsum[i] = s;
    }
    if ((lane & 3) == 0) {
        int r0 = lane >> 2;
        int rb = wn * 128 + wm * 32;
        red[rb + r0]          = rowsum[0];
        red[rb + r0 + 8]      = rowsum[1];
        red[rb + 16 + r0]     = rowsum[2];
        red[rb + 16 + r0 + 8] = rowsum[3];
    }
    __syncthreads();
    if (tid < 128) g_energy[m0 + tid] = red[tid] + red[128 + tid];
}

// ---------------- pass 3: masked (0/1) softmax over T ---------------------------
__global__ __launch_bounds__(256) void softmax_kernel(
    const int* __restrict__ x_lens, float* __restrict__ att)
{
    int b = blockIdx.x, tid = threadIdx.x;
    __shared__ float sm[T_];
    __shared__ float red[256];
    int len = x_lens[b];

    float mx = -3.4e38f;
    for (int t = tid; t < T_; t += 256) {
        float e = g_energy[b * T_ + t];
        e = (t < len) ? e : 0.0f;      // reference multiplies by 0/1 mask
        sm[t] = e;
        mx = fmaxf(mx, e);
    }
    red[tid] = mx; __syncthreads();
    for (int s = 128; s > 0; s >>= 1) {
        if (tid < s) red[tid] = fmaxf(red[tid], red[tid + s]);
        __syncthreads();
    }
    mx = red[0];
    __syncthreads();

    float lsum = 0.f;
    for (int t = tid; t < T_; t += 256) {
        float e = expf(sm[t] - mx);
        sm[t] = e;
        lsum += e;
    }
    red[tid] = lsum; __syncthreads();
    for (int s = 128; s > 0; s >>= 1) {
        if (tid < s) red[tid] += red[tid + s];
        __syncthreads();
    }
    float inv = 1.0f / red[0];
    for (int t = tid; t < T_; t += 256) att[b * T_ + t] = sm[t] * inv;
}

// ---------------- pass 4: context partials over T segments ----------------------
__global__ __launch_bounds__(128) void context_part_kernel(
    const float* __restrict__ enc, const float* __restrict__ att)
{
    int b = blockIdx.y, seg = blockIdx.z;
    int e = blockIdx.x * 128 + threadIdx.x;
    __shared__ float as_[T_ / 4];
    int t0 = seg * (T_ / 4);
    for (int t = threadIdx.x; t < T_ / 4; t += 128) as_[t] = att[b * T_ + t0 + t];
    __syncthreads();
    const float* ep = enc + ((size_t)b * T_ + t0) * E_ + e;
    float s = 0.f;
    #pragma unroll 8
    for (int t = 0; t < T_ / 4; ++t) s += ep[(size_t)t * E_] * as_[t];
    g_ctx_part[((size_t)seg * B_ + b) * E_ + e] = s;
}

__global__ __launch_bounds__(256) void context_reduce_kernel(float* __restrict__ ctx) {
    int i = blockIdx.x * 256 + threadIdx.x;      // over B_*E_
    ctx[i] = g_ctx_part[i] + g_ctx_part[B_ * E_ + i]
           + g_ctx_part[2 * B_ * E_ + i] + g_ctx_part[3 * B_ * E_ + i];
}

// ---------------- launch -------------------------------------------------------
extern "C" void kernel_launch(void* const* d_in, const int* in_sizes, int n_in,
                              void* d_out, int out_size)
{
    const float* enc     = (const float*)d_in[0];  // [B,T,E]
    const int*   x_lens  = (const int*)  d_in[1];  // [B]
    const float* dec_out = (const float*)d_in[2];  // [B,1,D]
    // d_in[3] att_weights_step: unused by reference
    const float* W_enc   = (const float*)d_in[4];  // [E,A]
    const float* b_enc   = (const float*)d_in[5];  // [A]
    const float* W_dec   = (const float*)d_in[6];  // [D,A]
    const float* v       = (const float*)d_in[7];  // [A]

    float* ctx = (float*)d_out;            // [B,1,E]
    float* att = (float*)d_out + B_ * E_;  // [B,T]

    cudaFuncSetAttribute(energy_kernel,
                         cudaFuncAttributeMaxDynamicSharedMemorySize, SMEM_TOTAL);

    convert_enc_kernel<<<(B_ * T_ * E_) / (256 * 4), 256>>>(enc);
    convert_wt_kernel <<<(A_ * E_) / 256, 256>>>(W_enc);
    dec_proj_kernel   <<<dim3(A_ / 256, B_), 256>>>(dec_out, W_dec, b_enc);
    energy_kernel     <<<(B_ * T_) / 128, 256, SMEM_TOTAL>>>(v);
    softmax_kernel    <<<B_, 256>>>(x_lens, att);
    context_part_kernel<<<dim3(E_ / 128, B_, 4), 128>>>(enc, att);
    context_reduce_kernel<<<(B_ * E_) / 256, 256>>>(ctx);
}

// round 9
// speedup vs baseline: 1.4668x; 1.3428x over previous
#include <cuda_runtime.h>
#include <cuda_bf16.h>
#include <math.h>
#include <stdint.h>

#define B_ 32
#define T_ 2048
#define E_ 1024
#define A_ 1024
#define D_ 1024

typedef unsigned int u32;
typedef unsigned long long u64;

// ---------------- scratch (device globals; allocations forbidden) --------------
__device__ __align__(256) __nv_bfloat16 g_enc_hi[(size_t)B_ * T_ * E_];
__device__ __align__(256) __nv_bfloat16 g_enc_lo[(size_t)B_ * T_ * E_];
__device__ __align__(256) __nv_bfloat16 g_Wt[A_ * E_];      // W^T [A,E], bf16 RN
__device__ float g_dec_proj[B_ * A_];
__device__ float g_energy[B_ * T_];
__device__ float g_ctx_part[4 * B_ * E_];

// ---------------- PTX helpers (baseline ISA only: sm_80-class) ------------------
__device__ __forceinline__ u32 smem_u32(const void* p) {
    u32 a; asm("{ .reg .u64 t; cvta.to.shared.u64 t, %1; cvt.u32.u64 %0, t; }" : "=r"(a) : "l"(p));
    return a;
}
__device__ __forceinline__ void cpa16(u32 dst, const void* src) {
    asm volatile("cp.async.cg.shared.global [%0], [%1], 16;" :: "r"(dst), "l"(src));
}
#define CPA_COMMIT()  asm volatile("cp.async.commit_group;" ::: "memory")
#define CPA_WAIT(n)   asm volatile("cp.async.wait_group %0;" :: "n"(n) : "memory")

__device__ __forceinline__ void ldsm4(u32* r, u32 addr) {
    asm volatile("ldmatrix.sync.aligned.m8n8.x4.shared.b16 {%0,%1,%2,%3}, [%4];"
        : "=r"(r[0]), "=r"(r[1]), "=r"(r[2]), "=r"(r[3]) : "r"(addr));
}
__device__ __forceinline__ void mma_bf16(float* c, const u32* a, const u32* b) {
    asm volatile("mma.sync.aligned.m16n8k16.row.col.f32.bf16.bf16.f32 "
        "{%0,%1,%2,%3}, {%4,%5,%6,%7}, {%8,%9}, {%0,%1,%2,%3};"
        : "+f"(c[0]), "+f"(c[1]), "+f"(c[2]), "+f"(c[3])
        : "r"(a[0]), "r"(a[1]), "r"(a[2]), "r"(a[3]), "r"(b[0]), "r"(b[1]));
}

// tanh via 2 MUFU: tanh(x) = (e - 1)/(e + 1), e = 2^(2x*log2e)
__device__ __forceinline__ float fast_tanh(float x) {
    float xa = fminf(fmaxf(x, -12.0f), 12.0f);
    float e;
    asm("ex2.approx.f32 %0, %1;" : "=f"(e) : "f"(xa * 2.8853900817779268f));
    float r;
    asm("rcp.approx.f32 %0, %1;" : "=f"(r) : "f"(e + 1.0f));
    return (e - 1.0f) * r;
}

// ---------------- pass 0a: enc fp32 -> bf16 hi/lo ------------------------------
__global__ __launch_bounds__(256) void convert_enc_kernel(const float* __restrict__ enc) {
    size_t i = ((size_t)blockIdx.x * 256 + threadIdx.x) * 4;
    float4 x = *(const float4*)(enc + i);
    __nv_bfloat16 h0 = __float2bfloat16(x.x), h1 = __float2bfloat16(x.y);
    __nv_bfloat16 h2 = __float2bfloat16(x.z), h3 = __float2bfloat16(x.w);
    __nv_bfloat16 l0 = __float2bfloat16(x.x - __bfloat162float(h0));
    __nv_bfloat16 l1 = __float2bfloat16(x.y - __bfloat162float(h1));
    __nv_bfloat16 l2 = __float2bfloat16(x.z - __bfloat162float(h2));
    __nv_bfloat16 l3 = __float2bfloat16(x.w - __bfloat162float(h3));
    *(__nv_bfloat162*)(g_enc_hi + i)     = __nv_bfloat162(h0, h1);
    *(__nv_bfloat162*)(g_enc_hi + i + 2) = __nv_bfloat162(h2, h3);
    *(__nv_bfloat162*)(g_enc_lo + i)     = __nv_bfloat162(l0, l1);
    *(__nv_bfloat162*)(g_enc_lo + i + 2) = __nv_bfloat162(l2, l3);
}

// ---------------- pass 0b: W_enc [E,A] -> W^T [A,E] bf16 (RN) -------------------
__global__ __launch_bounds__(256) void convert_wt_kernel(const float* __restrict__ W) {
    int idx = blockIdx.x * 256 + threadIdx.x;      // output-linear over [A,E]
    int a = idx >> 10, e = idx & 1023;
    g_Wt[idx] = __float2bfloat16(W[(size_t)e * A_ + a]);
}

// ---------------- pass 1: dec_proj[b,a] = dec[b,:] . W_dec[:,a] + b_enc[a] ------
// (kept fully fp32 — anchors the energy precision)
__global__ __launch_bounds__(256) void dec_proj_kernel(
    const float* __restrict__ dec_out, const float* __restrict__ W_dec,
    const float* __restrict__ b_enc)
{
    int b = blockIdx.y;
    int a = blockIdx.x * 256 + threadIdx.x;
    __shared__ float ds[D_];
    for (int i = threadIdx.x; i < D_; i += 256) ds[i] = dec_out[b * D_ + i];
    __syncthreads();
    float s = b_enc[a];
    #pragma unroll 8
    for (int d = 0; d < D_; ++d) s += ds[d] * W_dec[(size_t)d * A_ + a];
    g_dec_proj[b * A_ + a] = s;
}

// ---------------- pass 2: mma.sync 2-split bf16 GEMM + tanh + v-reduce ----------
// 256 thr = 8 warps (4M x 2N), 2 CTAs/SM. CTA tile M=128 x N=128/chunk, 8 chunks.
// KC=32 stages, depth-4 cp.async ring, ONE __syncthreads per stage.
// Rows 64B, granule-XOR swizzle off(row,g)=row*64+((g^(row>>1))&3)*16 =>
// conflict-free ldmatrix, no padding. Stage = Ahi+Alo+B = 24KB.
// 2 MMA splits: enc_hi*W + enc_lo*W  (W single bf16; err ~2^-9 -> rel_err ~1e-4).
#define KC 32
#define NSTAGE (E_/KC)               // 32 per chunk
#define TOTSTG (8 * NSTAGE)          // 256 flat
#define NPIPE 4
#define ROWB 64
#define SPLIT_SZ (128 * ROWB)        // 8192
#define STG_SZ (3 * SPLIT_SZ)        // 24576: Ahi, Alo, B
#define ST_AH 0
#define ST_AL SPLIT_SZ
#define ST_B  (2 * SPLIT_SZ)
#define OF_DP (NPIPE * STG_SZ)       // 98304
#define OF_V  (OF_DP + 4096)
#define OF_RED (OF_V + 4096)
#define SMEM_TOTAL (OF_RED + 1024)   // 107520 -> 2 CTAs/SM

__device__ __forceinline__ void stage_in(u32 sb, int s,
                                         const char* encH, const char* encL, int tid)
{
    const u32 base = sb + (u32)(s & (NPIPE - 1)) * STG_SZ;
    const int kbyte = (s & (NSTAGE - 1)) * 64;   // 32 bf16 = 64B along k
    const int a0 = (s >> 5) * 128;               // N-chunk base
    const int row = tid >> 1;
    const int xr  = (row >> 1) & 3;
    #pragma unroll
    for (int q = 0; q < 2; ++q) {
        const int g  = (tid & 1) * 2 + q;        // granule 0..3 along k
        const u32 so = (u32)(row * ROWB + ((g ^ xr) & 3) * 16);
        const int gc = kbyte + g * 16;
        size_t ga = (size_t)row * 2048 + gc;
        cpa16(base + ST_AH + so, encH + ga);
        cpa16(base + ST_AL + so, encL + ga);
        size_t gb = (size_t)(a0 + row) * 2048 + gc;
        cpa16(base + ST_B + so, (const char*)g_Wt + gb);
    }
}

__global__ __launch_bounds__(256, 2) void energy_kernel(const float* __restrict__ v) {
    extern __shared__ char smem[];
    u32 sb = smem_u32(smem);
    const int tid  = threadIdx.x;
    const int lane = tid & 31, wid = tid >> 5;
    const int wm = wid >> 1, wn = wid & 1;
    const int m0 = blockIdx.x * 128;           // flattened (b*T + t) row base
    const int b  = m0 >> 11;

    float* dp_s = (float*)(smem + OF_DP);
    float* v_s  = (float*)(smem + OF_V);
    float* red  = (float*)(smem + OF_RED);
    for (int i = tid; i < A_; i += 256) {
        dp_s[i] = g_dec_proj[b * A_ + i];
        v_s[i]  = v[i];
    }

    const char* encH = (const char*)g_enc_hi + (size_t)m0 * 2048;
    const char* encL = (const char*)g_enc_lo + (size_t)m0 * 2048;

    // ldmatrix lane addressing with XOR swizzle.
    u32 a_base[2], a_xr[2];
    #pragma unroll
    for (int tm = 0; tm < 2; ++tm) {
        int r = wm * 32 + (lane & 15) + tm * 16;
        a_base[tm] = (u32)(r * ROWB);
        a_xr[tm]   = (u32)((r >> 1) & 3);
    }
    const u32 a_gbit = (u32)((lane >> 4) & 1);
    u32 b_base[4], b_xr[4];
    #pragma unroll
    for (int p = 0; p < 4; ++p) {
        int r = wn * 64 + (lane & 7) + ((lane >> 4) & 1) * 8 + p * 16;
        b_base[p] = (u32)(r * ROWB);
        b_xr[p]   = (u32)((r >> 1) & 3);
    }
    const u32 b_gbit = (u32)((lane >> 3) & 1);

    float rowsum[4] = {0.f, 0.f, 0.f, 0.f};

    // prologue: fill pipeline depth-1 stages
    #pragma unroll
    for (int p = 0; p < NPIPE - 1; ++p) {
        stage_in(sb, p, encH, encL, tid);
        CPA_COMMIT();
    }

    for (int ch = 0; ch < 8; ++ch) {
        const int a0 = ch * 128;
        float c[2][8][4];
        #pragma unroll
        for (int tm = 0; tm < 2; ++tm)
            #pragma unroll
            for (int tn = 0; tn < 8; ++tn)
                #pragma unroll
                for (int q = 0; q < 4; ++q) c[tm][tn][q] = 0.f;

        for (int kc = 0; kc < NSTAGE; ++kc) {
            const int s = ch * NSTAGE + kc;
            CPA_WAIT(NPIPE - 2);        // stage s landed
            __syncthreads();            // also proves buf (s+NPIPE-1)%NPIPE free

            if (s + NPIPE - 1 < TOTSTG) {
                stage_in(sb, s + NPIPE - 1, encH, encL, tid);
                CPA_COMMIT();
            }

            const u32 base = sb + (u32)(s & (NPIPE - 1)) * STG_SZ;
            #pragma unroll
            for (int ks = 0; ks < 2; ++ks) {
                const u32 ga = (u32)(ks * 2) + a_gbit;
                const u32 gb = (u32)(ks * 2) + b_gbit;
                u32 ah[2][4], al[2][4];
                #pragma unroll
                for (int tm = 0; tm < 2; ++tm) {
                    u32 off = a_base[tm] + ((ga ^ a_xr[tm]) & 3) * 16;
                    ldsm4(ah[tm], base + ST_AH + off);
                    ldsm4(al[tm], base + ST_AL + off);
                }
                #pragma unroll
                for (int p = 0; p < 4; ++p) {
                    u32 off = b_base[p] + ((gb ^ b_xr[p]) & 3) * 16;
                    u32 th[4];
                    ldsm4(th, base + ST_B + off);
                    #pragma unroll
                    for (int tm = 0; tm < 2; ++tm) {
                        mma_bf16(c[tm][2*p],   ah[tm], th);
                        mma_bf16(c[tm][2*p],   al[tm], th);
                        mma_bf16(c[tm][2*p+1], ah[tm], th + 2);
                        mma_bf16(c[tm][2*p+1], al[tm], th + 2);
                    }
                }
            }
        }

        // epilogue (register-only): tanh(c + dec_proj) . v into per-row partials
        #pragma unroll
        for (int tm = 0; tm < 2; ++tm)
            #pragma unroll
            for (int tn = 0; tn < 8; ++tn) {
                int n = a0 + wn * 64 + tn * 8 + 2 * (lane & 3);
                float d0 = dp_s[n], d1 = dp_s[n + 1];
                float v0 = v_s[n],  v1 = v_s[n + 1];
                rowsum[tm*2+0] += fast_tanh(c[tm][tn][0] + d0) * v0
                                + fast_tanh(c[tm][tn][1] + d1) * v1;
                rowsum[tm*2+1] += fast_tanh(c[tm][tn][2] + d0) * v0
                                + fast_tanh(c[tm][tn][3] + d1) * v1;
            }
    }

    // reduce across the 4 lanes of each quad (disjoint n-columns)
    #pragma unroll
    for (int i = 0; i < 4; ++i) {
        float s = rowsum[i];
        s += __shfl_xor_sync(0xffffffffu, s, 1);
        s += __shfl_xor_sync(0xffffffffu, s, 2);
        rowsum[i] = s;
    }
    if ((lane & 3) == 0) {
        int r0 = lane >> 2;
        int rb = wn * 128 + wm * 32;
        red[rb + r0]          = rowsum[0];
        red[rb + r0 + 8]      = rowsum[1];
        red[rb + 16 + r0]     = rowsum[2];
        red[rb + 16 + r0 + 8] = rowsum[3];
    }
    __syncthreads();
    if (tid < 128) g_energy[m0 + tid] = red[tid] + red[128 + tid];
}

// ---------------- pass 3: masked (0/1) softmax over T ---------------------------
__global__ __launch_bounds__(256) void softmax_kernel(
    const int* __restrict__ x_lens, float* __restrict__ att)
{
    int b = blockIdx.x, tid = threadIdx.x;
    __shared__ float sm[T_];
    __shared__ float red[256];
    int len = x_lens[b];

    float mx = -3.4e38f;
    for (int t = tid; t < T_; t += 256) {
        float e = g_energy[b * T_ + t];
        e = (t < len) ? e : 0.0f;      // reference multiplies by 0/1 mask
        sm[t] = e;
        mx = fmaxf(mx, e);
    }
    red[tid] = mx; __syncthreads();
    for (int s = 128; s > 0; s >>= 1) {
        if (tid < s) red[tid] = fmaxf(red[tid], red[tid + s]);
        __syncthreads();
    }
    mx = red[0];
    __syncthreads();

    float lsum = 0.f;
    for (int t = tid; t < T_; t += 256) {
        float e = expf(sm[t] - mx);
        sm[t] = e;
        lsum += e;
    }
    red[tid] = lsum; __syncthreads();
    for (int s = 128; s > 0; s >>= 1) {
        if (tid < s) red[tid] += red[tid + s];
        __syncthreads();
    }
    float inv = 1.0f / red[0];
    for (int t = tid; t < T_; t += 256) att[b * T_ + t] = sm[t] * inv;
}

// ---------------- pass 4: context partials over T segments ----------------------
__global__ __launch_bounds__(128) void context_part_kernel(
    const float* __restrict__ enc, const float* __restrict__ att)
{
    int b = blockIdx.y, seg = blockIdx.z;
    int e = blockIdx.x * 128 + threadIdx.x;
    __shared__ float as_[T_ / 4];
    int t0 = seg * (T_ / 4);
    for (int t = threadIdx.x; t < T_ / 4; t += 128) as_[t] = att[b * T_ + t0 + t];
    __syncthreads();
    const float* ep = enc + ((size_t)b * T_ + t0) * E_ + e;
    float s = 0.f;
    #pragma unroll 8
    for (int t = 0; t < T_ / 4; ++t) s += ep[(size_t)t * E_] * as_[t];
    g_ctx_part[((size_t)seg * B_ + b) * E_ + e] = s;
}

__global__ __launch_bounds__(256) void context_reduce_kernel(float* __restrict__ ctx) {
    int i = blockIdx.x * 256 + threadIdx.x;      // over B_*E_
    ctx[i] = g_ctx_part[i] + g_ctx_part[B_ * E_ + i]
           + g_ctx_part[2 * B_ * E_ + i] + g_ctx_part[3 * B_ * E_ + i];
}

// ---------------- launch -------------------------------------------------------
extern "C" void kernel_launch(void* const* d_in, const int* in_sizes, int n_in,
                              void* d_out, int out_size)
{
    const float* enc     = (const float*)d_in[0];  // [B,T,E]
    const int*   x_lens  = (const int*)  d_in[1];  // [B]
    const float* dec_out = (const float*)d_in[2];  // [B,1,D]
    // d_in[3] att_weights_step: unused by reference
    const float* W_enc   = (const float*)d_in[4];  // [E,A]
    const float* b_enc   = (const float*)d_in[5];  // [A]
    const float* W_dec   = (const float*)d_in[6];  // [D,A]
    const float* v       = (const float*)d_in[7];  // [A]

    float* ctx = (float*)d_out;            // [B,1,E]
    float* att = (float*)d_out + B_ * E_;  // [B,T]

    cudaFuncSetAttribute(energy_kernel,
                         cudaFuncAttributeMaxDynamicSharedMemorySize, SMEM_TOTAL);

    convert_enc_kernel<<<(B_ * T_ * E_) / (256 * 4), 256>>>(enc);
    convert_wt_kernel <<<(A_ * E_) / 256, 256>>>(W_enc);
    dec_proj_kernel   <<<dim3(A_ / 256, B_), 256>>>(dec_out, W_dec, b_enc);
    energy_kernel     <<<(B_ * T_) / 128, 256, SMEM_TOTAL>>>(v);
    softmax_kernel    <<<B_, 256>>>(x_lens, att);
    context_part_kernel<<<dim3(E_ / 128, B_, 4), 128>>>(enc, att);
    context_reduce_kernel<<<(B_ * E_) / 256, 256>>>(ctx);
}

// round 10
// speedup vs baseline: 1.5602x; 1.0637x over previous
#include <cuda_runtime.h>
#include <cuda_bf16.h>
#include <math.h>
#include <stdint.h>

#define B_ 32
#define T_ 2048
#define E_ 1024
#define A_ 1024
#define D_ 1024

typedef unsigned int u32;
typedef unsigned long long u64;

// ---------------- scratch (device globals; allocations forbidden) --------------
__device__ __align__(256) __nv_bfloat16 g_enc_hi[(size_t)B_ * T_ * E_];
__device__ __align__(256) __nv_bfloat16 g_enc_lo[(size_t)B_ * T_ * E_];
__device__ __align__(256) __nv_bfloat16 g_Wt[A_ * E_];      // W^T [A,E], bf16 RN
__device__ float g_dec_proj[B_ * A_];
__device__ float g_energy[B_ * T_];
__device__ float g_ctx_part[4 * B_ * E_];

// ---------------- PTX helpers (baseline ISA only: sm_80-class) ------------------
__device__ __forceinline__ u32 smem_u32(const void* p) {
    u32 a; asm("{ .reg .u64 t; cvta.to.shared.u64 t, %1; cvt.u32.u64 %0, t; }" : "=r"(a) : "l"(p));
    return a;
}
__device__ __forceinline__ void cpa16(u32 dst, const void* src) {
    asm volatile("cp.async.cg.shared.global [%0], [%1], 16;" :: "r"(dst), "l"(src));
}
#define CPA_COMMIT()  asm volatile("cp.async.commit_group;" ::: "memory")
#define CPA_WAIT(n)   asm volatile("cp.async.wait_group %0;" :: "n"(n) : "memory")

__device__ __forceinline__ void ldsm4(u32* r, u32 addr) {
    asm volatile("ldmatrix.sync.aligned.m8n8.x4.shared.b16 {%0,%1,%2,%3}, [%4];"
        : "=r"(r[0]), "=r"(r[1]), "=r"(r[2]), "=r"(r[3]) : "r"(addr));
}
__device__ __forceinline__ void mma_bf16(float* c, const u32* a, const u32* b) {
    asm volatile("mma.sync.aligned.m16n8k16.row.col.f32.bf16.bf16.f32 "
        "{%0,%1,%2,%3}, {%4,%5,%6,%7}, {%8,%9}, {%0,%1,%2,%3};"
        : "+f"(c[0]), "+f"(c[1]), "+f"(c[2]), "+f"(c[3])
        : "r"(a[0]), "r"(a[1]), "r"(a[2]), "r"(a[3]), "r"(b[0]), "r"(b[1]));
}

// tanh via 2 MUFU: tanh(x) = (e - 1)/(e + 1), e = 2^(2x*log2e)
__device__ __forceinline__ float fast_tanh(float x) {
    float xa = fminf(fmaxf(x, -12.0f), 12.0f);
    float e;
    asm("ex2.approx.f32 %0, %1;" : "=f"(e) : "f"(xa * 2.8853900817779268f));
    float r;
    asm("rcp.approx.f32 %0, %1;" : "=f"(r) : "f"(e + 1.0f));
    return (e - 1.0f) * r;
}

// ---------------- pass 0a: enc fp32 -> bf16 hi/lo ------------------------------
__global__ __launch_bounds__(256) void convert_enc_kernel(const float* __restrict__ enc) {
    size_t i = ((size_t)blockIdx.x * 256 + threadIdx.x) * 4;
    float4 x = *(const float4*)(enc + i);
    __nv_bfloat16 h0 = __float2bfloat16(x.x), h1 = __float2bfloat16(x.y);
    __nv_bfloat16 h2 = __float2bfloat16(x.z), h3 = __float2bfloat16(x.w);
    __nv_bfloat16 l0 = __float2bfloat16(x.x - __bfloat162float(h0));
    __nv_bfloat16 l1 = __float2bfloat16(x.y - __bfloat162float(h1));
    __nv_bfloat16 l2 = __float2bfloat16(x.z - __bfloat162float(h2));
    __nv_bfloat16 l3 = __float2bfloat16(x.w - __bfloat162float(h3));
    *(__nv_bfloat162*)(g_enc_hi + i)     = __nv_bfloat162(h0, h1);
    *(__nv_bfloat162*)(g_enc_hi + i + 2) = __nv_bfloat162(h2, h3);
    *(__nv_bfloat162*)(g_enc_lo + i)     = __nv_bfloat162(l0, l1);
    *(__nv_bfloat162*)(g_enc_lo + i + 2) = __nv_bfloat162(l2, l3);
}

// ---------------- pass 0b: W_enc [E,A] -> W^T [A,E] bf16 (RN) -------------------
__global__ __launch_bounds__(256) void convert_wt_kernel(const float* __restrict__ W) {
    int idx = blockIdx.x * 256 + threadIdx.x;      // output-linear over [A,E]
    int a = idx >> 10, e = idx & 1023;
    g_Wt[idx] = __float2bfloat16(W[(size_t)e * A_ + a]);
}

// ---------------- pass 1: dec_proj[b,a] = dec[b,:] . W_dec[:,a] + b_enc[a] ------
__global__ __launch_bounds__(256) void dec_proj_kernel(
    const float* __restrict__ dec_out, const float* __restrict__ W_dec,
    const float* __restrict__ b_enc)
{
    int b = blockIdx.y;
    int a = blockIdx.x * 256 + threadIdx.x;
    __shared__ float ds[D_];
    for (int i = threadIdx.x; i < D_; i += 256) ds[i] = dec_out[b * D_ + i];
    __syncthreads();
    float s = b_enc[a];
    #pragma unroll 8
    for (int d = 0; d < D_; ++d) s += ds[d] * W_dec[(size_t)d * A_ + a];
    g_dec_proj[b * A_ + a] = s;
}

// ---------------- pass 2: mma.sync 2-split GEMM, M=256 CTA ----------------------
// 512 thr = 16 warps, each owns a 16-row M-slice; N-chunk=128 (8 chunks); per-warp
// per-ks: 2 A ldsm.x4 (hi/lo) + 8 B ldsm.x4, 32 MMAs. B fragments amortized over
// 2x M-work vs the old M=128 CTA => smem crossbar no longer binds.
// KC=32 stages, depth-4 cp.async ring, one __syncthreads per stage.
// Rows 64B, granule-XOR swizzle: conflict-free ldmatrix without padding.
#define MT 256
#define KC 32
#define NSTAGE (E_/KC)               // 32 per chunk
#define TOTSTG (8 * NSTAGE)          // 256 flat
#define NPIPE 4
#define ROWB 64
#define A_SPLIT (MT * ROWB)          // 16384
#define B_SZ (128 * ROWB)            // 8192
#define STG_SZ (2 * A_SPLIT + B_SZ)  // 40960
#define ST_AH 0
#define ST_AL A_SPLIT
#define ST_B  (2 * A_SPLIT)
#define OF_DP (NPIPE * STG_SZ)       // 163840
#define OF_V  (OF_DP + 4096)
#define SMEM_TOTAL (OF_V + 4096)     // 172032 -> 1 CTA/SM

__device__ __forceinline__ void stage_in(u32 sb, int s,
                                         const char* encH, const char* encL, int tid)
{
    const u32 base = sb + (u32)(s & (NPIPE - 1)) * STG_SZ;
    const int kbyte = (s & (NSTAGE - 1)) * 64;   // 32 bf16 = 64B along k
    const int a0 = (s >> 5) * 128;               // N-chunk base
    // A hi+lo: 256 rows x 4 granules = 1024 chunks per split, 2 per thread
    #pragma unroll
    for (int r = 0; r < 2; ++r) {
        int c   = tid + r * 512;
        int row = c >> 2, g = c & 3;
        u32 so  = (u32)(row * ROWB + ((g ^ (row >> 1)) & 3) * 16);
        size_t ga = (size_t)row * 2048 + kbyte + g * 16;
        cpa16(base + ST_AH + so, encH + ga);
        cpa16(base + ST_AL + so, encL + ga);
    }
    // B: 128 rows x 4 granules = 512 chunks, 1 per thread
    {
        int row = tid >> 2, g = tid & 3;
        u32 so  = (u32)(row * ROWB + ((g ^ (row >> 1)) & 3) * 16);
        size_t gb = (size_t)(a0 + row) * 2048 + kbyte + g * 16;
        cpa16(base + ST_B + so, (const char*)g_Wt + gb);
    }
}

__global__ __launch_bounds__(512, 1) void energy_kernel(const float* __restrict__ v) {
    extern __shared__ char smem[];
    u32 sb = smem_u32(smem);
    const int tid  = threadIdx.x;
    const int lane = tid & 31, wid = tid >> 5;   // wid 0..15 = M-slice
    const int m0 = blockIdx.x * MT;              // flattened (b*T + t) row base
    const int b  = m0 >> 11;

    float* dp_s = (float*)(smem + OF_DP);
    float* v_s  = (float*)(smem + OF_V);
    for (int i = tid; i < A_; i += 512) {
        dp_s[i] = g_dec_proj[b * A_ + i];
        v_s[i]  = v[i];
    }

    const char* encH = (const char*)g_enc_hi + (size_t)m0 * 2048;
    const char* encL = (const char*)g_enc_lo + (size_t)m0 * 2048;

    // ldmatrix lane addressing (XOR swizzle)
    const int a_row  = wid * 16 + (lane & 15);
    const u32 a_base = (u32)(a_row * ROWB);
    const u32 a_xr   = (u32)((a_row >> 1) & 3);
    const u32 a_gbit = (u32)((lane >> 4) & 1);
    const int b_row  = (lane & 7) + ((lane >> 4) & 1) * 8;   // + p*16
    const u32 b_gbit = (u32)((lane >> 3) & 1);

    float rs0 = 0.f, rs1 = 0.f;

    // prologue: fill pipeline depth-1 stages
    #pragma unroll
    for (int p = 0; p < NPIPE - 1; ++p) {
        stage_in(sb, p, encH, encL, tid);
        CPA_COMMIT();
    }

    for (int ch = 0; ch < 8; ++ch) {
        const int a0 = ch * 128;
        float c[16][4];
        #pragma unroll
        for (int nt = 0; nt < 16; ++nt)
            #pragma unroll
            for (int q = 0; q < 4; ++q) c[nt][q] = 0.f;

        for (int kc = 0; kc < NSTAGE; ++kc) {
            const int s = ch * NSTAGE + kc;
            CPA_WAIT(NPIPE - 2);        // stage s landed
            __syncthreads();            // also proves the refill target buf is free

            if (s + NPIPE - 1 < TOTSTG) {
                stage_in(sb, s + NPIPE - 1, encH, encL, tid);
                CPA_COMMIT();
            }

            const u32 base = sb + (u32)(s & (NPIPE - 1)) * STG_SZ;
            #pragma unroll
            for (int ks = 0; ks < 2; ++ks) {
                const u32 ga = (u32)(ks * 2) + a_gbit;
                const u32 gb = (u32)(ks * 2) + b_gbit;
                u32 ah[4], al[4];
                {
                    u32 off = a_base + ((ga ^ a_xr) & 3) * 16;
                    ldsm4(ah, base + ST_AH + off);
                    ldsm4(al, base + ST_AL + off);
                }
                #pragma unroll
                for (int p = 0; p < 8; ++p) {
                    int r = b_row + p * 16;
                    u32 off = (u32)(r * ROWB) + ((gb ^ ((u32)(r >> 1) & 3)) & 3) * 16;
                    u32 tb[4];
                    ldsm4(tb, base + ST_B + off);
                    mma_bf16(c[2*p],   ah, tb);
                    mma_bf16(c[2*p],   al, tb);
                    mma_bf16(c[2*p+1], ah, tb + 2);
                    mma_bf16(c[2*p+1], al, tb + 2);
                }
            }
        }

        // epilogue (register-only): tanh(c + dec_proj) . v into per-row partials
        #pragma unroll
        for (int nt = 0; nt < 16; ++nt) {
            int n = a0 + nt * 8 + 2 * (lane & 3);
            float d0 = dp_s[n], d1 = dp_s[n + 1];
            float v0 = v_s[n],  v1 = v_s[n + 1];
            rs0 += fast_tanh(c[nt][0] + d0) * v0 + fast_tanh(c[nt][1] + d1) * v1;
            rs1 += fast_tanh(c[nt][2] + d0) * v0 + fast_tanh(c[nt][3] + d1) * v1;
        }
    }

    // quad reduce (lanes lane&3 cover disjoint n-columns); each row owned by 1 warp
    rs0 += __shfl_xor_sync(0xffffffffu, rs0, 1);
    rs0 += __shfl_xor_sync(0xffffffffu, rs0, 2);
    rs1 += __shfl_xor_sync(0xffffffffu, rs1, 1);
    rs1 += __shfl_xor_sync(0xffffffffu, rs1, 2);
    if ((lane & 3) == 0) {
        int r = m0 + wid * 16 + (lane >> 2);
        g_energy[r]     = rs0;
        g_energy[r + 8] = rs1;
    }
}

// ---------------- pass 3: masked (0/1) softmax over T ---------------------------
__global__ __launch_bounds__(256) void softmax_kernel(
    const int* __restrict__ x_lens, float* __restrict__ att)
{
    int b = blockIdx.x, tid = threadIdx.x;
    __shared__ float sm[T_];
    __shared__ float red[256];
    int len = x_lens[b];

    float mx = -3.4e38f;
    for (int t = tid; t < T_; t += 256) {
        float e = g_energy[b * T_ + t];
        e = (t < len) ? e : 0.0f;      // reference multiplies by 0/1 mask
        sm[t] = e;
        mx = fmaxf(mx, e);
    }
    red[tid] = mx; __syncthreads();
    for (int s = 128; s > 0; s >>= 1) {
        if (tid < s) red[tid] = fmaxf(red[tid], red[tid + s]);
        __syncthreads();
    }
    mx = red[0];
    __syncthreads();

    float lsum = 0.f;
    for (int t = tid; t < T_; t += 256) {
        float e = expf(sm[t] - mx);
        sm[t] = e;
        lsum += e;
    }
    red[tid] = lsum; __syncthreads();
    for (int s = 128; s > 0; s >>= 1) {
        if (tid < s) red[tid] += red[tid + s];
        __syncthreads();
    }
    float inv = 1.0f / red[0];
    for (int t = tid; t < T_; t += 256) att[b * T_ + t] = sm[t] * inv;
}

// ---------------- pass 4: context partials over T segments ----------------------
__global__ __launch_bounds__(128) void context_part_kernel(
    const float* __restrict__ enc, const float* __restrict__ att)
{
    int b = blockIdx.y, seg = blockIdx.z;
    int e = blockIdx.x * 128 + threadIdx.x;
    __shared__ float as_[T_ / 4];
    int t0 = seg * (T_ / 4);
    for (int t = threadIdx.x; t < T_ / 4; t += 128) as_[t] = att[b * T_ + t0 + t];
    __syncthreads();
    const float* ep = enc + ((size_t)b * T_ + t0) * E_ + e;
    float s = 0.f;
    #pragma unroll 8
    for (int t = 0; t < T_ / 4; ++t) s += ep[(size_t)t * E_] * as_[t];
    g_ctx_part[((size_t)seg * B_ + b) * E_ + e] = s;
}

__global__ __launch_bounds__(256) void context_reduce_kernel(float* __restrict__ ctx) {
    int i = blockIdx.x * 256 + threadIdx.x;      // over B_*E_
    ctx[i] = g_ctx_part[i] + g_ctx_part[B_ * E_ + i]
           + g_ctx_part[2 * B_ * E_ + i] + g_ctx_part[3 * B_ * E_ + i];
}

// ---------------- launch -------------------------------------------------------
extern "C" void kernel_launch(void* const* d_in, const int* in_sizes, int n_in,
                              void* d_out, int out_size)
{
    const float* enc     = (const float*)d_in[0];  // [B,T,E]
    const int*   x_lens  = (const int*)  d_in[1];  // [B]
    const float* dec_out = (const float*)d_in[2];  // [B,1,D]
    // d_in[3] att_weights_step: unused by reference
    const float* W_enc   = (const float*)d_in[4];  // [E,A]
    const float* b_enc   = (const float*)d_in[5];  // [A]
    const float* W_dec   = (const float*)d_in[6];  // [D,A]
    const float* v       = (const float*)d_in[7];  // [A]

    float* ctx = (float*)d_out;            // [B,1,E]
    float* att = (float*)d_out + B_ * E_;  // [B,T]

    cudaFuncSetAttribute(energy_kernel,
                         cudaFuncAttributeMaxDynamicSharedMemorySize, SMEM_TOTAL);

    convert_enc_kernel<<<(B_ * T_ * E_) / (256 * 4), 256>>>(enc);
    convert_wt_kernel <<<(A_ * E_) / 256, 256>>>(W_enc);
    dec_proj_kernel   <<<dim3(A_ / 256, B_), 256>>>(dec_out, W_dec, b_enc);
    energy_kernel     <<<(B_ * T_) / MT, 512, SMEM_TOTAL>>>(v);
    softmax_kernel    <<<B_, 256>>>(x_lens, att);
    context_part_kernel<<<dim3(E_ / 128, B_, 4), 128>>>(enc, att);
    context_reduce_kernel<<<(B_ * E_) / 256, 256>>>(ctx);
}

// round 11
// speedup vs baseline: 2.2028x; 1.4118x over previous
#include <cuda_runtime.h>
#include <cuda_bf16.h>
#include <cuda_fp16.h>
#include <math.h>
#include <stdint.h>

#define B_ 32
#define T_ 2048
#define E_ 1024
#define A_ 1024
#define D_ 1024

typedef unsigned int u32;
typedef unsigned long long u64;

// ---------------- scratch (device globals; allocations forbidden) --------------
__device__ __align__(256) __half g_enc_h[(size_t)B_ * T_ * E_];  // enc fp16
__device__ __align__(256) __half g_Wt[A_ * E_];                  // W^T [A,E] fp16
__device__ float g_dec_proj[B_ * A_];
__device__ float g_energy[B_ * T_];
__device__ float g_ctx_part[4 * B_ * E_];

// ---------------- PTX helpers (baseline ISA only: sm_80-class) ------------------
__device__ __forceinline__ u32 smem_u32(const void* p) {
    u32 a; asm("{ .reg .u64 t; cvta.to.shared.u64 t, %1; cvt.u32.u64 %0, t; }" : "=r"(a) : "l"(p));
    return a;
}
__device__ __forceinline__ void cpa16(u32 dst, const void* src) {
    asm volatile("cp.async.cg.shared.global [%0], [%1], 16;" :: "r"(dst), "l"(src));
}
#define CPA_COMMIT()  asm volatile("cp.async.commit_group;" ::: "memory")
#define CPA_WAIT(n)   asm volatile("cp.async.wait_group %0;" :: "n"(n) : "memory")

__device__ __forceinline__ void ldsm4(u32* r, u32 addr) {
    asm volatile("ldmatrix.sync.aligned.m8n8.x4.shared.b16 {%0,%1,%2,%3}, [%4];"
        : "=r"(r[0]), "=r"(r[1]), "=r"(r[2]), "=r"(r[3]) : "r"(addr));
}
__device__ __forceinline__ void mma_f16(float* c, const u32* a, const u32* b) {
    asm volatile("mma.sync.aligned.m16n8k16.row.col.f32.f16.f16.f32 "
        "{%0,%1,%2,%3}, {%4,%5,%6,%7}, {%8,%9}, {%0,%1,%2,%3};"
        : "+f"(c[0]), "+f"(c[1]), "+f"(c[2]), "+f"(c[3])
        : "r"(a[0]), "r"(a[1]), "r"(a[2]), "r"(a[3]), "r"(b[0]), "r"(b[1]));
}

// tanh via 2 MUFU: tanh(x) = (e - 1)/(e + 1), e = 2^(2x*log2e)
__device__ __forceinline__ float fast_tanh(float x) {
    float xa = fminf(fmaxf(x, -12.0f), 12.0f);
    float e;
    asm("ex2.approx.f32 %0, %1;" : "=f"(e) : "f"(xa * 2.8853900817779268f));
    float r;
    asm("rcp.approx.f32 %0, %1;" : "=f"(r) : "f"(e + 1.0f));
    return (e - 1.0f) * r;
}

// ---------------- pass 0a: enc fp32 -> fp16 ------------------------------------
__global__ __launch_bounds__(256) void convert_enc_kernel(const float* __restrict__ enc) {
    size_t i = ((size_t)blockIdx.x * 256 + threadIdx.x) * 4;
    float4 x = *(const float4*)(enc + i);
    __half2 h01 = __floats2half2_rn(x.x, x.y);
    __half2 h23 = __floats2half2_rn(x.z, x.w);
    *(__half2*)(g_enc_h + i)     = h01;
    *(__half2*)(g_enc_h + i + 2) = h23;
}

// ---------------- pass 0b: W_enc [E,A] -> W^T [A,E] fp16 (RN) -------------------
__global__ __launch_bounds__(256) void convert_wt_kernel(const float* __restrict__ W) {
    int idx = blockIdx.x * 256 + threadIdx.x;      // output-linear over [A,E]
    int a = idx >> 10, e = idx & 1023;
    g_Wt[idx] = __float2half_rn(W[(size_t)e * A_ + a]);
}

// ---------------- pass 1: dec_proj[b,a] = dec[b,:] . W_dec[:,a] + b_enc[a] ------
// (fully fp32 — anchors the energy precision)
__global__ __launch_bounds__(256) void dec_proj_kernel(
    const float* __restrict__ dec_out, const float* __restrict__ W_dec,
    const float* __restrict__ b_enc)
{
    int b = blockIdx.y;
    int a = blockIdx.x * 256 + threadIdx.x;
    __shared__ float ds[D_];
    for (int i = threadIdx.x; i < D_; i += 256) ds[i] = dec_out[b * D_ + i];
    __syncthreads();
    float s = b_enc[a];
    #pragma unroll 8
    for (int d = 0; d < D_; ++d) s += ds[d] * W_dec[(size_t)d * A_ + a];
    g_dec_proj[b * A_ + a] = s;
}

// ---------------- pass 2: single fp16 mma.sync GEMM + tanh + v-reduce -----------
// 512 thr = 16 warps, each owns a 16-row M-slice of the M=256 CTA tile.
// N-chunk=128 (8 chunks); per warp per ks: 1 A ldsm.x4 + 8 B ldsm.x4, 16 MMAs.
// KC=32 stages, depth-4 cp.async ring, one __syncthreads per stage.
// Rows 64B, granule-XOR swizzle: conflict-free ldmatrix without padding.
// fp16 (10-bit mantissa) both operands, fp32 acc: rel_err ~2e-4 (5x margin).
#define MT 256
#define KC 32
#define NSTAGE (E_/KC)               // 32 per chunk
#define TOTSTG (8 * NSTAGE)          // 256 flat
#define NPIPE 4
#define ROWB 64
#define A_SZ (MT * ROWB)             // 16384
#define B_SZ (128 * ROWB)            // 8192
#define STG_SZ (A_SZ + B_SZ)         // 24576
#define ST_A 0
#define ST_B A_SZ
#define OF_DP (NPIPE * STG_SZ)       // 98304
#define OF_V  (OF_DP + 4096)
#define SMEM_TOTAL (OF_V + 4096)     // 106496 -> 1 CTA of 512 thr/SM

__device__ __forceinline__ void stage_in(u32 sb, int s,
                                         const char* encp, int tid)
{
    const u32 base = sb + (u32)(s & (NPIPE - 1)) * STG_SZ;
    const int kbyte = (s & (NSTAGE - 1)) * 64;   // 32 fp16 = 64B along k
    const int a0 = (s >> 5) * 128;               // N-chunk base
    // A: 256 rows x 4 granules = 1024 chunks of 16B, 2 per thread
    #pragma unroll
    for (int r = 0; r < 2; ++r) {
        int c   = tid + r * 512;
        int row = c >> 2, g = c & 3;
        u32 so  = (u32)(row * ROWB + ((g ^ (row >> 1)) & 3) * 16);
        size_t ga = (size_t)row * 2048 + kbyte + g * 16;
        cpa16(base + ST_A + so, encp + ga);
    }
    // B: 128 rows x 4 granules = 512 chunks, 1 per thread
    {
        int row = tid >> 2, g = tid & 3;
        u32 so  = (u32)(row * ROWB + ((g ^ (row >> 1)) & 3) * 16);
        size_t gb = (size_t)(a0 + row) * 2048 + kbyte + g * 16;
        cpa16(base + ST_B + so, (const char*)g_Wt + gb);
    }
}

__global__ __launch_bounds__(512, 1) void energy_kernel(const float* __restrict__ v) {
    extern __shared__ char smem[];
    u32 sb = smem_u32(smem);
    const int tid  = threadIdx.x;
    const int lane = tid & 31, wid = tid >> 5;   // wid 0..15 = M-slice
    const int m0 = blockIdx.x * MT;              // flattened (b*T + t) row base
    const int b  = m0 >> 11;

    float* dp_s = (float*)(smem + OF_DP);
    float* v_s  = (float*)(smem + OF_V);
    for (int i = tid; i < A_; i += 512) {
        dp_s[i] = g_dec_proj[b * A_ + i];
        v_s[i]  = v[i];
    }

    const char* encp = (const char*)g_enc_h + (size_t)m0 * 2048;

    // ldmatrix lane addressing (XOR swizzle)
    const int a_row  = wid * 16 + (lane & 15);
    const u32 a_base = (u32)(a_row * ROWB);
    const u32 a_xr   = (u32)((a_row >> 1) & 3);
    const u32 a_gbit = (u32)((lane >> 4) & 1);
    const int b_row  = (lane & 7) + ((lane >> 4) & 1) * 8;   // + p*16
    const u32 b_gbit = (u32)((lane >> 3) & 1);

    float rs0 = 0.f, rs1 = 0.f;

    // prologue: fill pipeline depth-1 stages
    #pragma unroll
    for (int p = 0; p < NPIPE - 1; ++p) {
        stage_in(sb, p, encp, tid);
        CPA_COMMIT();
    }

    for (int ch = 0; ch < 8; ++ch) {
        const int a0 = ch * 128;
        float c[16][4];
        #pragma unroll
        for (int nt = 0; nt < 16; ++nt)
            #pragma unroll
            for (int q = 0; q < 4; ++q) c[nt][q] = 0.f;

        for (int kc = 0; kc < NSTAGE; ++kc) {
            const int s = ch * NSTAGE + kc;
            CPA_WAIT(NPIPE - 2);        // stage s landed
            __syncthreads();            // also proves the refill target buf is free

            if (s + NPIPE - 1 < TOTSTG) {
                stage_in(sb, s + NPIPE - 1, encp, tid);
                CPA_COMMIT();
            }

            const u32 base = sb + (u32)(s & (NPIPE - 1)) * STG_SZ;
            #pragma unroll
            for (int ks = 0; ks < 2; ++ks) {
                const u32 ga = (u32)(ks * 2) + a_gbit;
                const u32 gb = (u32)(ks * 2) + b_gbit;
                u32 ah[4];
                {
                    u32 off = a_base + ((ga ^ a_xr) & 3) * 16;
                    ldsm4(ah, base + ST_A + off);
                }
                #pragma unroll
                for (int p = 0; p < 8; ++p) {
                    int r = b_row + p * 16;
                    u32 off = (u32)(r * ROWB) + ((gb ^ ((u32)(r >> 1) & 3)) & 3) * 16;
                    u32 tb[4];
                    ldsm4(tb, base + ST_B + off);
                    mma_f16(c[2*p],   ah, tb);
                    mma_f16(c[2*p+1], ah, tb + 2);
                }
            }
        }

        // epilogue (register-only): tanh(c + dec_proj) . v into per-row partials
        #pragma unroll
        for (int nt = 0; nt < 16; ++nt) {
            int n = a0 + nt * 8 + 2 * (lane & 3);
            float d0 = dp_s[n], d1 = dp_s[n + 1];
            float v0 = v_s[n],  v1 = v_s[n + 1];
            rs0 += fast_tanh(c[nt][0] + d0) * v0 + fast_tanh(c[nt][1] + d1) * v1;
            rs1 += fast_tanh(c[nt][2] + d0) * v0 + fast_tanh(c[nt][3] + d1) * v1;
        }
    }

    // quad reduce (lanes lane&3 cover disjoint n-columns); each row owned by 1 warp
    rs0 += __shfl_xor_sync(0xffffffffu, rs0, 1);
    rs0 += __shfl_xor_sync(0xffffffffu, rs0, 2);
    rs1 += __shfl_xor_sync(0xffffffffu, rs1, 1);
    rs1 += __shfl_xor_sync(0xffffffffu, rs1, 2);
    if ((lane & 3) == 0) {
        int r = m0 + wid * 16 + (lane >> 2);
        g_energy[r]     = rs0;
        g_energy[r + 8] = rs1;
    }
}

// ---------------- pass 3: masked (0/1) softmax over T ---------------------------
__global__ __launch_bounds__(256) void softmax_kernel(
    const int* __restrict__ x_lens, float* __restrict__ att)
{
    int b = blockIdx.x, tid = threadIdx.x;
    __shared__ float sm[T_];
    __shared__ float red[256];
    int len = x_lens[b];

    float mx = -3.4e38f;
    for (int t = tid; t < T_; t += 256) {
        float e = g_energy[b * T_ + t];
        e = (t < len) ? e : 0.0f;      // reference multiplies by 0/1 mask
        sm[t] = e;
        mx = fmaxf(mx, e);
    }
    red[tid] = mx; __syncthreads();
    for (int s = 128; s > 0; s >>= 1) {
        if (tid < s) red[tid] = fmaxf(red[tid], red[tid + s]);
        __syncthreads();
    }
    mx = red[0];
    __syncthreads();

    float lsum = 0.f;
    for (int t = tid; t < T_; t += 256) {
        float e = expf(sm[t] - mx);
        sm[t] = e;
        lsum += e;
    }
    red[tid] = lsum; __syncthreads();
    for (int s = 128; s > 0; s >>= 1) {
        if (tid < s) red[tid] += red[tid + s];
        __syncthreads();
    }
    float inv = 1.0f / red[0];
    for (int t = tid; t < T_; t += 256) att[b * T_ + t] = sm[t] * inv;
}

// ---------------- pass 4: context partials over T segments ----------------------
__global__ __launch_bounds__(128) void context_part_kernel(
    const float* __restrict__ enc, const float* __restrict__ att)
{
    int b = blockIdx.y, seg = blockIdx.z;
    int e = blockIdx.x * 128 + threadIdx.x;
    __shared__ float as_[T_ / 4];
    int t0 = seg * (T_ / 4);
    for (int t = threadIdx.x; t < T_ / 4; t += 128) as_[t] = att[b * T_ + t0 + t];
    __syncthreads();
    const float* ep = enc + ((size_t)b * T_ + t0) * E_ + e;
    float s = 0.f;
    #pragma unroll 8
    for (int t = 0; t < T_ / 4; ++t) s += ep[(size_t)t * E_] * as_[t];
    g_ctx_part[((size_t)seg * B_ + b) * E_ + e] = s;
}

__global__ __launch_bounds__(256) void context_reduce_kernel(float* __restrict__ ctx) {
    int i = blockIdx.x * 256 + threadIdx.x;      // over B_*E_
    ctx[i] = g_ctx_part[i] + g_ctx_part[B_ * E_ + i]
           + g_ctx_part[2 * B_ * E_ + i] + g_ctx_part[3 * B_ * E_ + i];
}

// ---------------- launch -------------------------------------------------------
extern "C" void kernel_launch(void* const* d_in, const int* in_sizes, int n_in,
                              void* d_out, int out_size)
{
    const float* enc     = (const float*)d_in[0];  // [B,T,E]
    const int*   x_lens  = (const int*)  d_in[1];  // [B]
    const float* dec_out = (const float*)d_in[2];  // [B,1,D]
    // d_in[3] att_weights_step: unused by reference
    const float* W_enc   = (const float*)d_in[4];  // [E,A]
    const float* b_enc   = (const float*)d_in[5];  // [A]
    const float* W_dec   = (const float*)d_in[6];  // [D,A]
    const float* v       = (const float*)d_in[7];  // [A]

    float* ctx = (float*)d_out;            // [B,1,E]
    float* att = (float*)d_out + B_ * E_;  // [B,T]

    cudaFuncSetAttribute(energy_kernel,
                         cudaFuncAttributeMaxDynamicSharedMemorySize, SMEM_TOTAL);

    convert_enc_kernel<<<(B_ * T_ * E_) / (256 * 4), 256>>>(enc);
    convert_wt_kernel <<<(A_ * E_) / 256, 256>>>(W_enc);
    dec_proj_kernel   <<<dim3(A_ / 256, B_), 256>>>(dec_out, W_dec, b_enc);
    energy_kernel     <<<(B_ * T_) / MT, 512, SMEM_TOTAL>>>(v);
    softmax_kernel    <<<B_, 256>>>(x_lens, att);
    context_part_kernel<<<dim3(E_ / 128, B_, 4), 128>>>(enc, att);
    context_reduce_kernel<<<(B_ * E_) / 256, 256>>>(ctx);
}

// round 12
// speedup vs baseline: 2.6507x; 1.2034x over previous
#include <cuda_runtime.h>
#include <cuda_fp16.h>
#include <math.h>
#include <stdint.h>

#define B_ 32
#define T_ 2048
#define E_ 1024
#define A_ 1024
#define D_ 1024

typedef unsigned int u32;
typedef unsigned long long u64;

// ---------------- scratch (device globals; allocations forbidden) --------------
__device__ __align__(256) __half g_enc_h[(size_t)B_ * T_ * E_];  // enc fp16
__device__ __align__(256) __half g_Wt[A_ * E_];                  // W^T [A,E] fp16
__device__ float g_dec_proj[B_ * A_];
__device__ float g_epart[8 * B_ * T_];     // per-N-chunk energy partials
__device__ float g_ctx_part[4 * B_ * E_];

// ---------------- PTX helpers (baseline ISA only: sm_80-class) ------------------
__device__ __forceinline__ u32 smem_u32(const void* p) {
    u32 a; asm("{ .reg .u64 t; cvta.to.shared.u64 t, %1; cvt.u32.u64 %0, t; }" : "=r"(a) : "l"(p));
    return a;
}
__device__ __forceinline__ void cpa16(u32 dst, const void* src) {
    asm volatile("cp.async.cg.shared.global [%0], [%1], 16;" :: "r"(dst), "l"(src));
}
#define CPA_COMMIT()  asm volatile("cp.async.commit_group;" ::: "memory")
#define CPA_WAIT(n)   asm volatile("cp.async.wait_group %0;" :: "n"(n) : "memory")

__device__ __forceinline__ void ldsm4(u32* r, u32 addr) {
    asm volatile("ldmatrix.sync.aligned.m8n8.x4.shared.b16 {%0,%1,%2,%3}, [%4];"
        : "=r"(r[0]), "=r"(r[1]), "=r"(r[2]), "=r"(r[3]) : "r"(addr));
}
__device__ __forceinline__ void mma_f16(float* c, const u32* a, const u32* b) {
    asm volatile("mma.sync.aligned.m16n8k16.row.col.f32.f16.f16.f32 "
        "{%0,%1,%2,%3}, {%4,%5,%6,%7}, {%8,%9}, {%0,%1,%2,%3};"
        : "+f"(c[0]), "+f"(c[1]), "+f"(c[2]), "+f"(c[3])
        : "r"(a[0]), "r"(a[1]), "r"(a[2]), "r"(a[3]), "r"(b[0]), "r"(b[1]));
}

// tanh via 2 MUFU: tanh(x) = (e - 1)/(e + 1), e = 2^(2x*log2e)
__device__ __forceinline__ float fast_tanh(float x) {
    float xa = fminf(fmaxf(x, -12.0f), 12.0f);
    float e;
    asm("ex2.approx.f32 %0, %1;" : "=f"(e) : "f"(xa * 2.8853900817779268f));
    float r;
    asm("rcp.approx.f32 %0, %1;" : "=f"(r) : "f"(e + 1.0f));
    return (e - 1.0f) * r;
}

// ---------------- pass 0a: enc fp32 -> fp16 ------------------------------------
__global__ __launch_bounds__(256) void convert_enc_kernel(const float* __restrict__ enc) {
    size_t i = ((size_t)blockIdx.x * 256 + threadIdx.x) * 4;
    float4 x = *(const float4*)(enc + i);
    *(__half2*)(g_enc_h + i)     = __floats2half2_rn(x.x, x.y);
    *(__half2*)(g_enc_h + i + 2) = __floats2half2_rn(x.z, x.w);
}

// ---------------- pass 0b: W_enc [E,A] -> W^T [A,E] fp16 (RN) -------------------
__global__ __launch_bounds__(256) void convert_wt_kernel(const float* __restrict__ W) {
    int idx = blockIdx.x * 256 + threadIdx.x;      // output-linear over [A,E]
    int a = idx >> 10, e = idx & 1023;
    g_Wt[idx] = __float2half_rn(W[(size_t)e * A_ + a]);
}

// ---------------- pass 1: dec_proj[b,a] = dec[b,:] . W_dec[:,a] + b_enc[a] ------
__global__ __launch_bounds__(256) void dec_proj_kernel(
    const float* __restrict__ dec_out, const float* __restrict__ W_dec,
    const float* __restrict__ b_enc)
{
    int b = blockIdx.y;
    int a = blockIdx.x * 256 + threadIdx.x;
    __shared__ float ds[D_];
    for (int i = threadIdx.x; i < D_; i += 256) ds[i] = dec_out[b * D_ + i];
    __syncthreads();
    float s = b_enc[a];
    #pragma unroll 8
    for (int d = 0; d < D_; ++d) s += ds[d] * W_dec[(size_t)d * A_ + a];
    g_dec_proj[b * A_ + a] = s;
}

// ---------------- pass 2: fp16 mma.sync GEMM, item-partitioned ------------------
// Work item = (m-tile of 256 rows, N-chunk of 128) -> 2048 items statically and
// contiguously partitioned over a fixed 152-CTA grid (13-14 items each; ~4% tail
// vs 16% with the old 256-CTA 2-wave launch). Each item's per-row partial energy
// is written once to g_epart[ch][row] (deterministic); softmax sums the 8 chunks.
// 512 thr = 16 warps as 8M x 2N (warp tile 32x64): per ks 2 A + 4 B ldsm.x4 and
// 32 MMAs per stage (LDSM/stage 12 vs 18 of the 16x128 layout).
// KC=32 stages, depth-4 cp.async ring (always-commit), one __syncthreads/stage.
// Rows 64B, granule-XOR swizzle: conflict-free ldmatrix without padding.
#define MT 256
#define NITEM 2048
#define GRID_E 152
#define NPIPE 4
#define ROWB 64
#define A_SZ (MT * ROWB)             // 16384
#define B_SZ (128 * ROWB)            // 8192
#define STG_SZ (A_SZ + B_SZ)         // 24576
#define ST_A 0
#define ST_B A_SZ
#define OF_DP (NPIPE * STG_SZ)       // 98304
#define OF_V  (OF_DP + 4096)
#define OF_RED (OF_V + 4096)
#define SMEM_TOTAL (OF_RED + 2048)   // 108544 -> 1 CTA of 512 thr/SM

__device__ __forceinline__ void stage_in(u32 sb, u32 w0, u32 f, int tid) {
    const u32 w  = w0 + (f >> 5);                // item
    const u32 kc = f & 31;
    const u32 base = sb + (f & 3) * STG_SZ;
    const size_t mbyte = (size_t)(w >> 3) * (MT * 2048);
    const u32 a0 = (w & 7) * 128;
    const int kbyte = (int)kc * 64;              // 32 fp16 = 64B along k
    const char* encp = (const char*)g_enc_h + mbyte;
    // A: 256 rows x 4 granules = 1024 chunks of 16B, 2 per thread
    #pragma unroll
    for (int r = 0; r < 2; ++r) {
        int cc  = tid + r * 512;
        int row = cc >> 2, g = cc & 3;
        u32 so  = (u32)(row * ROWB + ((g ^ (row >> 1)) & 3) * 16);
        cpa16(base + ST_A + so, encp + (size_t)row * 2048 + kbyte + g * 16);
    }
    // B: 128 rows x 4 granules = 512 chunks, 1 per thread
    {
        int row = tid >> 2, g = tid & 3;
        u32 so  = (u32)(row * ROWB + ((g ^ (row >> 1)) & 3) * 16);
        cpa16(base + ST_B + so,
              (const char*)g_Wt + (size_t)(a0 + row) * 2048 + kbyte + g * 16);
    }
}

__global__ __launch_bounds__(512, 1) void energy_kernel(const float* __restrict__ v) {
    extern __shared__ char smem[];
    u32 sb = smem_u32(smem);
    const int tid  = threadIdx.x;
    const int lane = tid & 31, wid = tid >> 5;
    const int wm = wid >> 1, wn = wid & 1;       // 8M x 2N warp grid

    const u32 cta = blockIdx.x;
    const u32 w0 = (cta * NITEM) / GRID_E;
    const u32 w1 = ((cta + 1) * NITEM) / GRID_E;
    const u32 nst = (w1 - w0) * 32;

    float* dp_s = (float*)(smem + OF_DP);
    float* v_s  = (float*)(smem + OF_V);
    float* red  = (float*)(smem + OF_RED);
    for (int i = tid; i < A_; i += 512) v_s[i] = v[i];

    // ldmatrix lane addressing (XOR swizzle)
    const int a_row  = wm * 32 + (lane & 15);            // + tm*16
    const u32 a_gbit = (u32)((lane >> 4) & 1);
    const int b_row  = wn * 64 + (lane & 7) + ((lane >> 4) & 1) * 8;  // + p*16
    const u32 b_gbit = (u32)((lane >> 3) & 1);

    // prologue: fill pipeline depth-1 stages
    #pragma unroll
    for (u32 p = 0; p < NPIPE - 1; ++p) {
        stage_in(sb, w0, p, tid);
        CPA_COMMIT();
    }

    for (u32 w = w0; w < w1; ++w) {
        const int m0 = (int)(w >> 3) << 8;
        const int ch = (int)(w & 7);
        const int b  = m0 >> 11;
        const int a0 = ch * 128;

        float c_[2][8][4];
        #pragma unroll
        for (int tm = 0; tm < 2; ++tm)
            #pragma unroll
            for (int tn = 0; tn < 8; ++tn)
                #pragma unroll
                for (int q = 0; q < 4; ++q) c_[tm][tn][q] = 0.f;

        for (u32 kc = 0; kc < 32; ++kc) {
            const u32 f = (w - w0) * 32 + kc;
            CPA_WAIT(2);                // stage f landed (always-commit keeps count exact)
            __syncthreads();            // frees refill target; orders dp_s/red reuse

            if (kc == 0) {              // item's batch row: load dec_proj (b may change)
                dp_s[tid]       = g_dec_proj[b * A_ + tid];
                dp_s[tid + 512] = g_dec_proj[b * A_ + tid + 512];
            }
            if (f + NPIPE - 1 < nst) stage_in(sb, w0, f + NPIPE - 1, tid);
            CPA_COMMIT();               // possibly-empty group: keeps wait(2) exact

            const u32 base = sb + (f & 3) * STG_SZ;
            #pragma unroll
            for (int ks = 0; ks < 2; ++ks) {
                const u32 ga = (u32)(ks * 2) + a_gbit;
                const u32 gb = (u32)(ks * 2) + b_gbit;
                u32 ah[2][4];
                #pragma unroll
                for (int tm = 0; tm < 2; ++tm) {
                    int r = a_row + tm * 16;
                    u32 off = (u32)(r * ROWB) + ((ga ^ ((u32)(r >> 1) & 3)) & 3) * 16;
                    ldsm4(ah[tm], base + ST_A + off);
                }
                #pragma unroll
                for (int p = 0; p < 4; ++p) {
                    int r = b_row + p * 16;
                    u32 off = (u32)(r * ROWB) + ((gb ^ ((u32)(r >> 1) & 3)) & 3) * 16;
                    u32 tb[4];
                    ldsm4(tb, base + ST_B + off);
                    #pragma unroll
                    for (int tm = 0; tm < 2; ++tm) {
                        mma_f16(c_[tm][2*p],   ah[tm], tb);
                        mma_f16(c_[tm][2*p+1], ah[tm], tb + 2);
                    }
                }
            }
        }

        // epilogue: tanh(c + dec_proj) . v, reduce quad + across the 2 N-warps
        float rowsum[4] = {0.f, 0.f, 0.f, 0.f};
        #pragma unroll
        for (int tm = 0; tm < 2; ++tm)
            #pragma unroll
            for (int tn = 0; tn < 8; ++tn) {
                int n = a0 + wn * 64 + tn * 8 + 2 * (lane & 3);
                float d0 = dp_s[n & 1023], d1 = dp_s[(n & 1023) + 1];
                float v0 = v_s[n & 1023],  v1 = v_s[(n & 1023) + 1];
                rowsum[tm*2+0] += fast_tanh(c_[tm][tn][0] + d0) * v0
                                + fast_tanh(c_[tm][tn][1] + d1) * v1;
                rowsum[tm*2+1] += fast_tanh(c_[tm][tn][2] + d0) * v0
                                + fast_tanh(c_[tm][tn][3] + d1) * v1;
            }
        #pragma unroll
        for (int i = 0; i < 4; ++i) {
            float s = rowsum[i];
            s += __shfl_xor_sync(0xffffffffu, s, 1);
            s += __shfl_xor_sync(0xffffffffu, s, 2);
            rowsum[i] = s;
        }
        if ((lane & 3) == 0) {
            int r0 = lane >> 2;
            int rb = wn * 256 + wm * 32;
            red[rb + r0]          = rowsum[0];
            red[rb + r0 + 8]      = rowsum[1];
            red[rb + 16 + r0]     = rowsum[2];
            red[rb + 16 + r0 + 8] = rowsum[3];
        }
        __syncthreads();
        if (tid < 256)
            g_epart[ch * (B_ * T_) + m0 + tid] = red[tid] + red[256 + tid];
    }
}

// ---------------- pass 3: sum chunk partials + masked (0/1) softmax -------------
__global__ __launch_bounds__(256) void softmax_kernel(
    const int* __restrict__ x_lens, float* __restrict__ att)
{
    int b = blockIdx.x, tid = threadIdx.x;
    __shared__ float sm[T_];
    __shared__ float red[256];
    int len = x_lens[b];

    float mx = -3.4e38f;
    for (int t = tid; t < T_; t += 256) {
        int r = b * T_ + t;
        float e = 0.f;
        #pragma unroll
        for (int ch = 0; ch < 8; ++ch) e += g_epart[ch * (B_ * T_) + r];
        e = (t < len) ? e : 0.0f;      // reference multiplies by 0/1 mask
        sm[t] = e;
        mx = fmaxf(mx, e);
    }
    red[tid] = mx; __syncthreads();
    for (int s = 128; s > 0; s >>= 1) {
        if (tid < s) red[tid] = fmaxf(red[tid], red[tid + s]);
        __syncthreads();
    }
    mx = red[0];
    __syncthreads();

    float lsum = 0.f;
    for (int t = tid; t < T_; t += 256) {
        float e = expf(sm[t] - mx);
        sm[t] = e;
        lsum += e;
    }
    red[tid] = lsum; __syncthreads();
    for (int s = 128; s > 0; s >>= 1) {
        if (tid < s) red[tid] += red[tid + s];
        __syncthreads();
    }
    float inv = 1.0f / red[0];
    for (int t = tid; t < T_; t += 256) att[b * T_ + t] = sm[t] * inv;
}

// ---------------- pass 4: context partials over T segments (fp16 enc) -----------
__global__ __launch_bounds__(128) void context_part_kernel(const float* __restrict__ att) {
    int b = blockIdx.y, seg = blockIdx.z;
    int e2 = blockIdx.x * 128 + threadIdx.x;     // half2 column index (E/2 = 512)
    __shared__ float as_[T_ / 4];
    int t0 = seg * (T_ / 4);
    for (int t = threadIdx.x; t < T_ / 4; t += 128) as_[t] = att[b * T_ + t0 + t];
    __syncthreads();
    const __half2* ep = (const __half2*)g_enc_h + ((size_t)b * T_ + t0) * (E_ / 2) + e2;
    float s0 = 0.f, s1 = 0.f;
    #pragma unroll 8
    for (int t = 0; t < T_ / 4; ++t) {
        float2 f = __half22float2(ep[(size_t)t * (E_ / 2)]);
        s0 += f.x * as_[t];
        s1 += f.y * as_[t];
    }
    float2* out = (float2*)&g_ctx_part[((size_t)seg * B_ + b) * E_];
    out[e2] = make_float2(s0, s1);
}

__global__ __launch_bounds__(256) void context_reduce_kernel(float* __restrict__ ctx) {
    int i = blockIdx.x * 256 + threadIdx.x;      // over B_*E_
    ctx[i] = g_ctx_part[i] + g_ctx_part[B_ * E_ + i]
           + g_ctx_part[2 * B_ * E_ + i] + g_ctx_part[3 * B_ * E_ + i];
}

// ---------------- launch -------------------------------------------------------
extern "C" void kernel_launch(void* const* d_in, const int* in_sizes, int n_in,
                              void* d_out, int out_size)
{
    const float* enc     = (const float*)d_in[0];  // [B,T,E]
    const int*   x_lens  = (const int*)  d_in[1];  // [B]
    const float* dec_out = (const float*)d_in[2];  // [B,1,D]
    // d_in[3] att_weights_step: unused by reference
    const float* W_enc   = (const float*)d_in[4];  // [E,A]
    const float* b_enc   = (const float*)d_in[5];  // [A]
    const float* W_dec   = (const float*)d_in[6];  // [D,A]
    const float* v       = (const float*)d_in[7];  // [A]

    float* ctx = (float*)d_out;            // [B,1,E]
    float* att = (float*)d_out + B_ * E_;  // [B,T]

    cudaFuncSetAttribute(energy_kernel,
                         cudaFuncAttributeMaxDynamicSharedMemorySize, SMEM_TOTAL);

    convert_enc_kernel<<<(B_ * T_ * E_) / (256 * 4), 256>>>(enc);
    convert_wt_kernel <<<(A_ * E_) / 256, 256>>>(W_enc);
    dec_proj_kernel   <<<dim3(A_ / 256, B_), 256>>>(dec_out, W_dec, b_enc);
    energy_kernel     <<<GRID_E, 512, SMEM_TOTAL>>>(v);
    softmax_kernel    <<<B_, 256>>>(x_lens, att);
    context_part_kernel<<<dim3(E_ / 256, B_, 4), 128>>>(att);
    context_reduce_kernel<<<(B_ * E_) / 256, 256>>>(ctx);
}

// round 13
// speedup vs baseline: 2.7837x; 1.0502x over previous
#include <cuda_runtime.h>
#include <cuda_fp16.h>
#include <math.h>
#include <stdint.h>

#define B_ 32
#define T_ 2048
#define E_ 1024
#define A_ 1024
#define D_ 1024

typedef unsigned int u32;
typedef unsigned long long u64;

// ---------------- scratch (device globals; allocations forbidden) --------------
__device__ __align__(256) __half g_enc_h[(size_t)B_ * T_ * E_];  // enc fp16
__device__ __align__(256) __half g_Wt[A_ * E_];                  // W^T [A,E] fp16
__device__ float g_dec_proj[B_ * A_];
__device__ float g_epart[8 * B_ * T_];     // per-N-chunk energy partials
__device__ float g_ctx_part[8 * B_ * E_];

// ---------------- PTX helpers (baseline ISA only: sm_80-class) ------------------
__device__ __forceinline__ u32 smem_u32(const void* p) {
    u32 a; asm("{ .reg .u64 t; cvta.to.shared.u64 t, %1; cvt.u32.u64 %0, t; }" : "=r"(a) : "l"(p));
    return a;
}
__device__ __forceinline__ void cpa16(u32 dst, const void* src) {
    asm volatile("cp.async.cg.shared.global [%0], [%1], 16;" :: "r"(dst), "l"(src));
}
#define CPA_COMMIT()  asm volatile("cp.async.commit_group;" ::: "memory")
#define CPA_WAIT(n)   asm volatile("cp.async.wait_group %0;" :: "n"(n) : "memory")

__device__ __forceinline__ void ldsm4(u32* r, u32 addr) {
    asm volatile("ldmatrix.sync.aligned.m8n8.x4.shared.b16 {%0,%1,%2,%3}, [%4];"
        : "=r"(r[0]), "=r"(r[1]), "=r"(r[2]), "=r"(r[3]) : "r"(addr));
}
__device__ __forceinline__ void mma_f16(float* c, const u32* a, const u32* b) {
    asm volatile("mma.sync.aligned.m16n8k16.row.col.f32.f16.f16.f32 "
        "{%0,%1,%2,%3}, {%4,%5,%6,%7}, {%8,%9}, {%0,%1,%2,%3};"
        : "+f"(c[0]), "+f"(c[1]), "+f"(c[2]), "+f"(c[3])
        : "r"(a[0]), "r"(a[1]), "r"(a[2]), "r"(a[3]), "r"(b[0]), "r"(b[1]));
}

// tanh via 2 MUFU: tanh(x) = (e - 1)/(e + 1), e = 2^(2x*log2e)
__device__ __forceinline__ float fast_tanh(float x) {
    float xa = fminf(fmaxf(x, -12.0f), 12.0f);
    float e;
    asm("ex2.approx.f32 %0, %1;" : "=f"(e) : "f"(xa * 2.8853900817779268f));
    float r;
    asm("rcp.approx.f32 %0, %1;" : "=f"(r) : "f"(e + 1.0f));
    return (e - 1.0f) * r;
}

// ---------------- pass 0a: enc fp32 -> fp16 (8 elems/thread, 16B store) ---------
__global__ __launch_bounds__(256) void convert_enc_kernel(const float* __restrict__ enc) {
    size_t i = ((size_t)blockIdx.x * 256 + threadIdx.x) * 8;
    float4 x = *(const float4*)(enc + i);
    float4 y = *(const float4*)(enc + i + 4);
    __half2 h[4] = { __floats2half2_rn(x.x, x.y), __floats2half2_rn(x.z, x.w),
                     __floats2half2_rn(y.x, y.y), __floats2half2_rn(y.z, y.w) };
    *(uint4*)(g_enc_h + i) = *(uint4*)h;
}

// ---------------- pass 0b: W_enc [E,A] -> W^T [A,E] fp16 (RN) -------------------
__global__ __launch_bounds__(256) void convert_wt_kernel(const float* __restrict__ W) {
    int idx = blockIdx.x * 256 + threadIdx.x;      // output-linear over [A,E]
    int a = idx >> 10, e = idx & 1023;
    g_Wt[idx] = __float2half_rn(W[(size_t)e * A_ + a]);
}

// ---------------- pass 1: dec_proj[b,a] = dec[b,:] . W_dec[:,a] + b_enc[a] ------
__global__ __launch_bounds__(256) void dec_proj_kernel(
    const float* __restrict__ dec_out, const float* __restrict__ W_dec,
    const float* __restrict__ b_enc)
{
    int b = blockIdx.y;
    int a = blockIdx.x * 256 + threadIdx.x;
    __shared__ float ds[D_];
    for (int i = threadIdx.x; i < D_; i += 256) ds[i] = dec_out[b * D_ + i];
    __syncthreads();
    float s = b_enc[a];
    #pragma unroll 8
    for (int d = 0; d < D_; ++d) s += ds[d] * W_dec[(size_t)d * A_ + a];
    g_dec_proj[b * A_ + a] = s;
}

// ---------------- pass 2: fp16 mma.sync GEMM, item-partitioned ------------------
// Work item = (m-tile 256 rows, N-chunk 128): 2048 items over a fixed 152-CTA
// grid. 512 thr = 16 warps as 8M x 2N (warp tile 32x64). KC=32 stages, depth-4
// cp.async ring (always-commit), one __syncthreads per stage. Rows 64B with
// granule-XOR swizzle. ALL addresses strength-reduced to per-thread constants:
// inner-loop address math is add + (off ^ ks*32) only. dec_proj read directly
// in the epilogue (L2-resident) — no smem staging, no per-stage branch.
#define MT 256
#define NITEM 2048
#define GRID_E 152
#define NPIPE 4
#define ROWB 64
#define A_SZ (MT * ROWB)             // 16384
#define B_SZ (128 * ROWB)            // 8192
#define STG_SZ (A_SZ + B_SZ)         // 24576
#define ST_A 0
#define ST_B A_SZ
#define OF_V  (NPIPE * STG_SZ)       // 98304
#define OF_RED (OF_V + 4096)
#define SMEM_TOTAL (OF_RED + 2048)   // 104448 -> 1 CTA of 512 thr/SM

__global__ __launch_bounds__(512, 1) void energy_kernel(const float* __restrict__ v) {
    extern __shared__ char smem[];
    u32 sb = smem_u32(smem);
    const int tid  = threadIdx.x;
    const int lane = tid & 31, wid = tid >> 5;
    const int wm = wid >> 1, wn = wid & 1;       // 8M x 2N warp grid

    const u32 cta = blockIdx.x;
    const u32 w0 = (cta * NITEM) / GRID_E;
    const u32 w1 = ((cta + 1) * NITEM) / GRID_E;
    const u32 nst = (w1 - w0) * 32;

    float* v_s  = (float*)(smem + OF_V);
    float* red  = (float*)(smem + OF_RED);
    for (int i = tid; i < A_; i += 512) v_s[i] = v[i];

    // ---- per-thread constant addressing (strength reduction) ----
    // stage_in constants: A chunks r0/r1, B chunk
    const int arow0 = tid >> 2,        ag0 = tid & 3;
    const int arow1 = (tid + 512) >> 2, ag1 = ag0;           // same g, row+128
    const int brow  = tid >> 2,        bg  = tid & 3;
    const u32 soA0 = (u32)(arow0 * ROWB + ((ag0 ^ (arow0 >> 1)) & 3) * 16);
    const u32 soA1 = (u32)(arow1 * ROWB + ((ag1 ^ (arow1 >> 1)) & 3) * 16);
    const u32 soB  = (u32)(brow * ROWB + ((bg ^ (brow >> 1)) & 3) * 16);
    const u32 cgA0 = (u32)(arow0 * 2048 + ag0 * 16);         // global byte consts
    const u32 cgA1 = (u32)(arow1 * 2048 + ag1 * 16);
    const u32 cgB  = (u32)(brow * 2048 + bg * 16);

    // ldsm constants: offsets for ks=0; ks=1 = off ^ 32
    const u32 a_gbit = (u32)((lane >> 4) & 1);
    const u32 b_gbit = (u32)((lane >> 3) & 1);
    u32 loA[2], loB[4];
    #pragma unroll
    for (int tm = 0; tm < 2; ++tm) {
        int r = wm * 32 + (lane & 15) + tm * 16;
        loA[tm] = (u32)(r * ROWB) + ((a_gbit ^ ((u32)(r >> 1) & 3)) & 3) * 16;
    }
    #pragma unroll
    for (int p = 0; p < 4; ++p) {
        int r = wn * 64 + (lane & 7) + ((lane >> 4) & 1) * 8 + p * 16;
        loB[p] = (u32)(r * ROWB) + ((b_gbit ^ ((u32)(r >> 1) & 3)) & 3) * 16;
    }

    // stage issue: all addresses from consts + f
    auto stage_in = [&](u32 f) {
        const u32 w  = w0 + (f >> 5);
        const u32 base = sb + (f & 3) * STG_SZ;
        const u32 kbyte = (f & 31) * 64;
        const char* encp = (const char*)g_enc_h + ((size_t)(w >> 3) << 19);
        const char* wp   = (const char*)g_Wt + ((size_t)(w & 7) << 18);
        cpa16(base + ST_A + soA0, encp + cgA0 + kbyte);
        cpa16(base + ST_A + soA1, encp + cgA1 + kbyte);
        cpa16(base + ST_B + soB,  wp   + cgB  + kbyte);
    };

    // prologue: fill pipeline depth-1 stages
    #pragma unroll
    for (u32 p = 0; p < NPIPE - 1; ++p) {
        stage_in(p);
        CPA_COMMIT();
    }

    for (u32 w = w0; w < w1; ++w) {
        const int m0 = (int)(w >> 3) << 8;
        const int ch = (int)(w & 7);
        const int b  = m0 >> 11;
        const int a0 = ch * 128;

        float c_[2][8][4];
        #pragma unroll
        for (int tm = 0; tm < 2; ++tm)
            #pragma unroll
            for (int tn = 0; tn < 8; ++tn)
                #pragma unroll
                for (int q = 0; q < 4; ++q) c_[tm][tn][q] = 0.f;

        for (u32 kc = 0; kc < 32; ++kc) {
            const u32 f = (w - w0) * 32 + kc;
            CPA_WAIT(2);                // stage f landed (always-commit keeps count exact)
            __syncthreads();            // frees refill target; orders red reuse

            if (f + NPIPE - 1 < nst) stage_in(f + NPIPE - 1);
            CPA_COMMIT();               // possibly-empty group keeps wait(2) exact

            const u32 baseA = sb + (f & 3) * STG_SZ + ST_A;
            const u32 baseB = sb + (f & 3) * STG_SZ + ST_B;
            #pragma unroll
            for (int ks = 0; ks < 2; ++ks) {
                const u32 kx = (u32)(ks * 32);   // granule-parity flip = XOR 32
                u32 ah[2][4];
                #pragma unroll
                for (int tm = 0; tm < 2; ++tm)
                    ldsm4(ah[tm], baseA + (loA[tm] ^ kx));
                #pragma unroll
                for (int p = 0; p < 4; ++p) {
                    u32 tb[4];
                    ldsm4(tb, baseB + (loB[p] ^ kx));
                    #pragma unroll
                    for (int tm = 0; tm < 2; ++tm) {
                        mma_f16(c_[tm][2*p],   ah[tm], tb);
                        mma_f16(c_[tm][2*p+1], ah[tm], tb + 2);
                    }
                }
            }
        }

        // epilogue: tanh(c + dec_proj) . v ; dec_proj via direct L2-resident LDG
        float rowsum[4] = {0.f, 0.f, 0.f, 0.f};
        const int nbase = a0 + wn * 64 + 2 * (lane & 3);
        #pragma unroll
        for (int tn = 0; tn < 8; ++tn) {
            int n = nbase + tn * 8;
            float2 d = *(const float2*)&g_dec_proj[b * A_ + n];
            float2 vv = *(const float2*)&v_s[n];
            #pragma unroll
            for (int tm = 0; tm < 2; ++tm) {
                rowsum[tm*2+0] += fast_tanh(c_[tm][tn][0] + d.x) * vv.x
                                + fast_tanh(c_[tm][tn][1] + d.y) * vv.y;
                rowsum[tm*2+1] += fast_tanh(c_[tm][tn][2] + d.x) * vv.x
                                + fast_tanh(c_[tm][tn][3] + d.y) * vv.y;
            }
        }
        #pragma unroll
        for (int i = 0; i < 4; ++i) {
            float s = rowsum[i];
            s += __shfl_xor_sync(0xffffffffu, s, 1);
            s += __shfl_xor_sync(0xffffffffu, s, 2);
            rowsum[i] = s;
        }
        if ((lane & 3) == 0) {
            int r0 = lane >> 2;
            int rb = wn * 256 + wm * 32;
            red[rb + r0]          = rowsum[0];
            red[rb + r0 + 8]      = rowsum[1];
            red[rb + 16 + r0]     = rowsum[2];
            red[rb + 16 + r0 + 8] = rowsum[3];
        }
        __syncthreads();
        if (tid < 256)
            g_epart[ch * (B_ * T_) + m0 + tid] = red[tid] + red[256 + tid];
    }
}

// ---------------- pass 3: sum chunk partials + masked (0/1) softmax -------------
__global__ __launch_bounds__(256) void softmax_kernel(
    const int* __restrict__ x_lens, float* __restrict__ att)
{
    int b = blockIdx.x, tid = threadIdx.x;
    __shared__ float sm[T_];
    __shared__ float red[256];
    int len = x_lens[b];

    float mx = -3.4e38f;
    for (int t = tid; t < T_; t += 256) {
        int r = b * T_ + t;
        float e = 0.f;
        #pragma unroll
        for (int ch = 0; ch < 8; ++ch) e += g_epart[ch * (B_ * T_) + r];
        e = (t < len) ? e : 0.0f;      // reference multiplies by 0/1 mask
        sm[t] = e;
        mx = fmaxf(mx, e);
    }
    red[tid] = mx; __syncthreads();
    for (int s = 128; s > 0; s >>= 1) {
        if (tid < s) red[tid] = fmaxf(red[tid], red[tid + s]);
        __syncthreads();
    }
    mx = red[0];
    __syncthreads();

    float lsum = 0.f;
    for (int t = tid; t < T_; t += 256) {
        float e = expf(sm[t] - mx);
        sm[t] = e;
        lsum += e;
    }
    red[tid] = lsum; __syncthreads();
    for (int s = 128; s > 0; s >>= 1) {
        if (tid < s) red[tid] += red[tid + s];
        __syncthreads();
    }
    float inv = 1.0f / red[0];
    for (int t = tid; t < T_; t += 256) att[b * T_ + t] = sm[t] * inv;
}

// ---------------- pass 4: context partials over 8 T-segments (fp16 enc) ---------
__global__ __launch_bounds__(256) void context_part_kernel(const float* __restrict__ att) {
    int b = blockIdx.y, seg = blockIdx.z;
    int e2 = threadIdx.x;                        // + 256 for second column
    __shared__ float as_[T_ / 8];
    int t0 = seg * (T_ / 8);
    as_[threadIdx.x] = att[b * T_ + t0 + threadIdx.x];
    __syncthreads();
    const __half2* ep = (const __half2*)g_enc_h + ((size_t)b * T_ + t0) * (E_ / 2);
    float s0 = 0.f, s1 = 0.f, s2 = 0.f, s3 = 0.f;
    #pragma unroll 8
    for (int t = 0; t < T_ / 8; ++t) {
        const __half2* row = ep + (size_t)t * (E_ / 2);
        float2 f0 = __half22float2(row[e2]);
        float2 f1 = __half22float2(row[e2 + 256]);
        float a = as_[t];
        s0 += f0.x * a; s1 += f0.y * a;
        s2 += f1.x * a; s3 += f1.y * a;
    }
    float2* out = (float2*)&g_ctx_part[((size_t)seg * B_ + b) * E_];
    out[e2]       = make_float2(s0, s1);
    out[e2 + 256] = make_float2(s2, s3);
}

__global__ __launch_bounds__(256) void context_reduce_kernel(float* __restrict__ ctx) {
    int i = blockIdx.x * 256 + threadIdx.x;      // over B_*E_
    float s = 0.f;
    #pragma unroll
    for (int seg = 0; seg < 8; ++seg) s += g_ctx_part[seg * (B_ * E_) + i];
    ctx[i] = s;
}

// ---------------- launch -------------------------------------------------------
extern "C" void kernel_launch(void* const* d_in, const int* in_sizes, int n_in,
                              void* d_out, int out_size)
{
    const float* enc     = (const float*)d_in[0];  // [B,T,E]
    const int*   x_lens  = (const int*)  d_in[1];  // [B]
    const float* dec_out = (const float*)d_in[2];  // [B,1,D]
    // d_in[3] att_weights_step: unused by reference
    const float* W_enc   = (const float*)d_in[4];  // [E,A]
    const float* b_enc   = (const float*)d_in[5];  // [A]
    const float* W_dec   = (const float*)d_in[6];  // [D,A]
    const float* v       = (const float*)d_in[7];  // [A]

    float* ctx = (float*)d_out;            // [B,1,E]
    float* att = (float*)d_out + B_ * E_;  // [B,T]

    cudaFuncSetAttribute(energy_kernel,
                         cudaFuncAttributeMaxDynamicSharedMemorySize, SMEM_TOTAL);

    convert_enc_kernel<<<(B_ * T_ * E_) / (256 * 8), 256>>>(enc);
    convert_wt_kernel <<<(A_ * E_) / 256, 256>>>(W_enc);
    dec_proj_kernel   <<<dim3(A_ / 256, B_), 256>>>(dec_out, W_dec, b_enc);
    energy_kernel     <<<GRID_E, 512, SMEM_TOTAL>>>(v);
    softmax_kernel    <<<B_, 256>>>(x_lens, att);
    context_part_kernel<<<dim3(1, B_, 8), 256>>>(att);
    context_reduce_kernel<<<(B_ * E_) / 256, 256>>>(ctx);
}